// round 1
// baseline (speedup 1.0000x reference)
#include <cuda_runtime.h>
#include <math.h>

// Problem dims
#define B_  256
#define T_  128
#define F_  128
#define H_  512
#define G4H 2048   // 4*H
#define K2F 256    // 2*F
#define KTOT 768   // F (c_c) + F (m) + H (h_dec)

// ---------------- persistent device state / scratch ----------------
__device__ float  g_gammah[T_ * B_ * H_];   // [t][b][j]  exp(-relu(d @ td_h_W^T + b))
__device__ float  g_alpha [T_ * B_ * F_];   // [t][b][f]  sigmoid([gamma_x, m] @ wc_W^T + b)
__device__ float  g_h    [B_ * H_];
__device__ float  g_c    [B_ * H_];
__device__ float  g_hdec [B_ * H_];
__device__ float  g_cc   [B_ * F_];
__device__ float  g_gates[B_ * G4H];
__device__ float  g_histT[H_ * F_];         // histT[k][f] = hist_W[f][k]
__device__ float  g_featT[F_ * F_];         // featT[k][f] = feat_W[f][k], diag zeroed
__device__ float  g_denom[T_];
__device__ double g_loss;

// ---------------- init: zero state, transpose weights ----------------
__global__ void k_init(const float* __restrict__ feat_W, const float* __restrict__ hist_W) {
    int idx = blockIdx.x * blockDim.x + threadIdx.x;   // 131072 threads
    if (idx < B_ * H_) { g_h[idx] = 0.f; g_c[idx] = 0.f; }
    if (idx == 0) g_loss = 0.0;
    if (idx < F_ * F_) {
        int k = idx >> 7, f = idx & 127;
        g_featT[idx] = (f == k) ? 0.f : feat_W[f * F_ + k];
    }
    if (idx < H_ * F_) {
        int k = idx >> 7, f = idx & 127;
        g_histT[idx] = hist_W[f * H_ + k];
    }
}

// ---------------- denom[t] = sum(target_mask[:,t,:]) + 1e-8 ----------------
__global__ void k_denom(const float* __restrict__ ev_all) {
    int t = blockIdx.x;
    float s = 0.f;
    for (int i = threadIdx.x; i < B_ * F_; i += 256) {
        int b = i >> 7, f = i & 127;
        s += ev_all[(b * T_ + t) * F_ + f];
    }
    #pragma unroll
    for (int off = 16; off > 0; off >>= 1) s += __shfl_down_sync(0xffffffffu, s, off);
    __shared__ float rs[8];
    int lane = threadIdx.x & 31, w = threadIdx.x >> 5;
    if (lane == 0) rs[w] = s;
    __syncthreads();
    if (threadIdx.x == 0) {
        float tot = 0.f;
        #pragma unroll
        for (int i = 0; i < 8; i++) tot += rs[i];
        g_denom[t] = tot + 1e-8f;
    }
}

// ---------------- generic tile params (shared by the 3 GEMM kernels) ----------------
#define BM 32
#define BN 64
#define BK 32
// 128 threads, each computes a 4x4 micro-tile.

// ---------------- P1: gamma_h for all (t,b) ----------------
// out[rr*512+n], rr = t*256+b; A row = d[(b*T+t)*F + k]; Bmat = td_h_W[n*F+k]
__global__ __launch_bounds__(128) void k_gammah(const float* __restrict__ d_all,
                                                const float* __restrict__ W,
                                                const float* __restrict__ bias) {
    __shared__ float sA[BM][BK + 1];
    __shared__ float sB[BK][BN + 1];
    const int rr0 = blockIdx.y * BM;
    const int bn  = blockIdx.x * BN;
    const int tid = threadIdx.x;
    const int tr = tid >> 4, tc = tid & 15;
    float acc[4][4] = {};
    for (int k0 = 0; k0 < F_; k0 += BK) {
        #pragma unroll
        for (int i = tid; i < BM * BK; i += 128) {
            int r = i >> 5, kk = i & 31;
            int rr = rr0 + r;
            int b = rr & 255, tt = rr >> 8;
            sA[r][kk] = d_all[(b * T_ + tt) * F_ + k0 + kk];
        }
        #pragma unroll
        for (int i = tid; i < BK * BN; i += 128) {
            int nl = i >> 5, kk = i & 31;
            sB[kk][nl] = W[(bn + nl) * F_ + k0 + kk];
        }
        __syncthreads();
        #pragma unroll
        for (int kk = 0; kk < BK; kk++) {
            float a[4], bb[4];
            #pragma unroll
            for (int i = 0; i < 4; i++) a[i] = sA[tr * 4 + i][kk];
            #pragma unroll
            for (int j = 0; j < 4; j++) bb[j] = sB[kk][tc * 4 + j];
            #pragma unroll
            for (int i = 0; i < 4; i++)
                #pragma unroll
                for (int j = 0; j < 4; j++) acc[i][j] += a[i] * bb[j];
        }
        __syncthreads();
    }
    #pragma unroll
    for (int i = 0; i < 4; i++) {
        int rr = rr0 + tr * 4 + i;
        #pragma unroll
        for (int j = 0; j < 4; j++) {
            int n = bn + tc * 4 + j;
            float v = acc[i][j] + bias[n];
            g_gammah[rr * H_ + n] = expf(-fmaxf(v, 0.f));
        }
    }
}

// ---------------- P2: alpha for all (t,b) ----------------
// A: k<128 -> gamma_x computed on the fly from d; k>=128 -> m. Bmat = wc_W[n*256+k]
__global__ __launch_bounds__(128) void k_alpha(const float* __restrict__ d_all,
                                               const float* __restrict__ m_all,
                                               const float* __restrict__ tdx_W,
                                               const float* __restrict__ tdx_b,
                                               const float* __restrict__ wc_W,
                                               const float* __restrict__ wc_b) {
    __shared__ float sA[BM][BK + 1];
    __shared__ float sB[BK][BN + 1];
    const int rr0 = blockIdx.y * BM;
    const int bn  = blockIdx.x * BN;
    const int tid = threadIdx.x;
    const int tr = tid >> 4, tc = tid & 15;
    float acc[4][4] = {};
    for (int k0 = 0; k0 < K2F; k0 += BK) {
        #pragma unroll
        for (int i = tid; i < BM * BK; i += 128) {
            int r = i >> 5, kk = i & 31;
            int rr = rr0 + r;
            int b = rr & 255, tt = rr >> 8;
            int k = k0 + kk;
            float v;
            if (k < F_) {
                float dv = d_all[(b * T_ + tt) * F_ + k];
                float gv = dv * tdx_W[k * F_ + k] + tdx_b[k];
                v = expf(-fmaxf(gv, 0.f));
            } else {
                v = m_all[(b * T_ + tt) * F_ + (k - F_)];
            }
            sA[r][kk] = v;
        }
        #pragma unroll
        for (int i = tid; i < BK * BN; i += 128) {
            int nl = i >> 5, kk = i & 31;
            sB[kk][nl] = wc_W[(bn + nl) * K2F + k0 + kk];
        }
        __syncthreads();
        #pragma unroll
        for (int kk = 0; kk < BK; kk++) {
            float a[4], bb[4];
            #pragma unroll
            for (int i = 0; i < 4; i++) a[i] = sA[tr * 4 + i][kk];
            #pragma unroll
            for (int j = 0; j < 4; j++) bb[j] = sB[kk][tc * 4 + j];
            #pragma unroll
            for (int i = 0; i < 4; i++)
                #pragma unroll
                for (int j = 0; j < 4; j++) acc[i][j] += a[i] * bb[j];
        }
        __syncthreads();
    }
    #pragma unroll
    for (int i = 0; i < 4; i++) {
        int rr = rr0 + tr * 4 + i;
        #pragma unroll
        for (int j = 0; j < 4; j++) {
            int n = bn + tc * 4 + j;
            float s = acc[i][j] + wc_b[n];
            g_alpha[rr * F_ + n] = 1.f / (1.f + expf(-s));
        }
    }
}

// ---------------- per-step fused pre-LSTM kernel ----------------
// 64 blocks x 128 threads, 4 batch rows per block.
__global__ __launch_bounds__(128) void k_step_pre(
    const float* __restrict__ x_all, const float* __restrict__ m_all,
    const float* __restrict__ tx_all, const float* __restrict__ ev_all,
    const float* __restrict__ hist_b, const float* __restrict__ feat_b,
    float* __restrict__ out, int t) {
    __shared__ float hdec_s[4][H_];
    __shared__ float xc_s[4][F_];
    __shared__ float red_s[4];
    const int b0 = blockIdx.x * 4;
    const int f = threadIdx.x;

    // h_dec = h * gamma_h[t]
    for (int i = f; i < 4 * H_; i += 128) {
        int r = i >> 9, j = i & 511;
        int b = b0 + r;
        float v = g_h[b * H_ + j] * g_gammah[(t * B_ + b) * H_ + j];
        hdec_s[r][j] = v;
        g_hdec[b * H_ + j] = v;
    }
    __syncthreads();

    // x_hist = h_dec @ hist_W^T + hist_b  (coalesced via transposed weights)
    float acc[4] = {0.f, 0.f, 0.f, 0.f};
    for (int k = 0; k < H_; k++) {
        float w = g_histT[k * F_ + f];
        #pragma unroll
        for (int r = 0; r < 4; r++) acc[r] += hdec_s[r][k] * w;
    }
    float hb = hist_b[f];
    float xh[4], mr[4], xr[4];
    #pragma unroll
    for (int r = 0; r < 4; r++) {
        int b = b0 + r;
        xh[r] = acc[r] + hb;
        int base = (b * T_ + t) * F_ + f;
        mr[r] = m_all[base];
        xr[r] = x_all[base];
        xc_s[r][f] = mr[r] * xr[r] + (1.f - mr[r]) * xh[r];
    }
    __syncthreads();

    // z_h = x_c @ (feat_W*offdiag)^T + feat_b
    float acc2[4] = {0.f, 0.f, 0.f, 0.f};
    for (int k = 0; k < F_; k++) {
        float w = g_featT[k * F_ + f];   // diag already zeroed
        #pragma unroll
        for (int r = 0; r < 4; r++) acc2[r] += xc_s[r][k] * w;
    }
    float fb = feat_b[f];
    float lsum = 0.f;
    #pragma unroll
    for (int r = 0; r < 4; r++) {
        int b = b0 + r;
        float z  = acc2[r] + fb;
        float al = g_alpha[(t * B_ + b) * F_ + f];
        float ch = al * z + (1.f - al) * xh[r];
        float cc = mr[r] * xr[r] + (1.f - mr[r]) * ch;
        g_cc[b * F_ + f] = cc;
        int base = (b * T_ + t) * F_ + f;
        out[base] = cc;                       // imputation output [B,T,F]
        float ev = ev_all[base], tg = tx_all[base];
        float e1 = xh[r] - tg, e2 = z - tg, e3 = ch - tg;
        lsum += ev * (e1 * e1 + e2 * e2 + e3 * e3);
    }
    // block-reduce loss, scale by 1/(denom[t]*T)
    #pragma unroll
    for (int off = 16; off > 0; off >>= 1) lsum += __shfl_down_sync(0xffffffffu, lsum, off);
    int lane = f & 31, w = f >> 5;
    if (lane == 0) red_s[w] = lsum;
    __syncthreads();
    if (f == 0) {
        float tot = red_s[0] + red_s[1] + red_s[2] + red_s[3];
        atomicAdd(&g_loss, (double)tot / ((double)g_denom[t] * (double)T_));
    }
}

// ---------------- per-step gates GEMM: C[256,2048] = [c_c | m_t | h_dec] @ [W_ih | W_hh]^T ----------------
__global__ __launch_bounds__(128) void k_gates(const float* __restrict__ W_ih,
                                               const float* __restrict__ W_hh,
                                               const float* __restrict__ b_ih,
                                               const float* __restrict__ b_hh,
                                               const float* __restrict__ m_all, int t) {
    __shared__ float sA[BM][BK + 1];
    __shared__ float sB[BK][BN + 1];
    const int bm = blockIdx.y * BM;
    const int bn = blockIdx.x * BN;
    const int tid = threadIdx.x;
    const int tr = tid >> 4, tc = tid & 15;
    float acc[4][4] = {};
    for (int k0 = 0; k0 < KTOT; k0 += BK) {
        #pragma unroll
        for (int i = tid; i < BM * BK; i += 128) {
            int r = i >> 5, kk = i & 31;
            int k = k0 + kk, b = bm + r;
            float v;
            if (k < F_)            v = g_cc[b * F_ + k];
            else if (k < K2F)      v = m_all[(b * T_ + t) * F_ + (k - F_)];
            else                   v = g_hdec[b * H_ + (k - K2F)];
            sA[r][kk] = v;
        }
        #pragma unroll
        for (int i = tid; i < BK * BN; i += 128) {
            int nl = i >> 5, kk = i & 31;
            int k = k0 + kk, n = bn + nl;
            sB[kk][nl] = (k < K2F) ? W_ih[n * K2F + k] : W_hh[n * H_ + (k - K2F)];
        }
        __syncthreads();
        #pragma unroll
        for (int kk = 0; kk < BK; kk++) {
            float a[4], bb[4];
            #pragma unroll
            for (int i = 0; i < 4; i++) a[i] = sA[tr * 4 + i][kk];
            #pragma unroll
            for (int j = 0; j < 4; j++) bb[j] = sB[kk][tc * 4 + j];
            #pragma unroll
            for (int i = 0; i < 4; i++)
                #pragma unroll
                for (int j = 0; j < 4; j++) acc[i][j] += a[i] * bb[j];
        }
        __syncthreads();
    }
    #pragma unroll
    for (int i = 0; i < 4; i++) {
        int b = bm + tr * 4 + i;
        #pragma unroll
        for (int j = 0; j < 4; j++) {
            int n = bn + tc * 4 + j;
            g_gates[b * G4H + n] = acc[i][j] + b_ih[n] + b_hh[n];
        }
    }
}

// ---------------- per-step LSTM pointwise update ----------------
__global__ __launch_bounds__(256) void k_lstm() {
    int idx = blockIdx.x * 256 + threadIdx.x;    // 131072 = B*H
    int b = idx >> 9, j = idx & 511;
    const float* g = g_gates + b * G4H;
    float ig = g[j], fg = g[H_ + j], gg = g[2 * H_ + j], og = g[3 * H_ + j];
    float si = 1.f / (1.f + expf(-ig));
    float sf = 1.f / (1.f + expf(-fg));
    float so = 1.f / (1.f + expf(-og));
    float c  = sf * g_c[idx] + si * tanhf(gg);
    g_c[idx] = c;
    g_h[idx] = so * tanhf(c);
}

// ---------------- finalize: write loss scalar ----------------
__global__ void k_finish(float* __restrict__ out, int out_size) {
    out[out_size - 1] = (float)g_loss;
}

// ---------------- launch ----------------
extern "C" void kernel_launch(void* const* d_in, const int* in_sizes, int n_in,
                              void* d_out, int out_size) {
    const float* x      = (const float*)d_in[0];
    const float* m      = (const float*)d_in[1];
    const float* d      = (const float*)d_in[2];
    const float* tx     = (const float*)d_in[3];
    const float* ev     = (const float*)d_in[4];
    const float* td_h_W = (const float*)d_in[5];
    const float* td_h_b = (const float*)d_in[6];
    const float* td_x_W = (const float*)d_in[7];
    const float* td_x_b = (const float*)d_in[8];
    const float* hist_W = (const float*)d_in[9];
    const float* hist_b = (const float*)d_in[10];
    const float* feat_W = (const float*)d_in[11];
    const float* feat_b = (const float*)d_in[12];
    const float* wc_W   = (const float*)d_in[13];
    const float* wc_b   = (const float*)d_in[14];
    const float* W_ih   = (const float*)d_in[15];
    const float* W_hh   = (const float*)d_in[16];
    const float* b_ih   = (const float*)d_in[17];
    const float* b_hh   = (const float*)d_in[18];
    float* out = (float*)d_out;

    k_init<<<512, 256>>>(feat_W, hist_W);
    k_denom<<<T_, 256>>>(ev);
    // gamma_h: M=32768 rows (t*256+b), N=512
    k_gammah<<<dim3(H_ / BN, (T_ * B_) / BM), 128>>>(d, td_h_W, td_h_b);
    // alpha: M=32768 rows, N=128
    k_alpha<<<dim3(F_ / BN, (T_ * B_) / BM), 128>>>(d, m, td_x_W, td_x_b, wc_W, wc_b);

    for (int t = 0; t < T_; t++) {
        k_step_pre<<<B_ / 4, 128>>>(x, m, tx, ev, hist_b, feat_b, out, t);
        k_gates<<<dim3(G4H / BN, B_ / BM), 128>>>(W_ih, W_hh, b_ih, b_hh, m, t);
        k_lstm<<<(B_ * H_) / 256, 256>>>();
    }
    k_finish<<<1, 1>>>(out, out_size);
}

// round 2
// speedup vs baseline: 1.9593x; 1.9593x over previous
#include <cuda_runtime.h>
#include <math.h>

// Problem dims
#define B_  256
#define T_  128
#define F_  128
#define H_  512
#define G4H 2048   // 4*H
#define GRID_MAIN 128
#define THREADS_MAIN 256

// ---------------- persistent device state / scratch ----------------
__device__ float  g_gammah[T_ * B_ * H_];   // [t][b][j]
__device__ float  g_alpha [T_ * B_ * F_];   // [t][b][f]
__device__ float  g_c    [B_ * H_];
__device__ float  g_hdec [B_ * H_];         // h * gamma_h[t]  (h never stored raw)
__device__ float  g_xhist[B_ * F_];
__device__ float  g_xc   [B_ * F_];
__device__ float  g_cc   [B_ * F_];
__device__ float  g_featT[F_ * F_];         // featT[k][f] = feat_W[f][k], diag zeroed
__device__ float  g_denom[T_];
__device__ double g_loss;
// grid barrier state
__device__ unsigned g_bar_count;
__device__ unsigned g_gen;

// ---------------- init ----------------
__global__ void k_init(const float* __restrict__ feat_W) {
    int idx = blockIdx.x * blockDim.x + threadIdx.x;   // 131072 threads
    if (idx < B_ * H_) { g_hdec[idx] = 0.f; g_c[idx] = 0.f; }
    if (idx == 0) { g_loss = 0.0; g_bar_count = 0u; g_gen = 0u; }
    if (idx < F_ * F_) {
        int k = idx >> 7, f = idx & 127;
        g_featT[idx] = (f == k) ? 0.f : feat_W[f * F_ + k];
    }
}

// ---------------- denom[t] ----------------
__global__ void k_denom(const float* __restrict__ ev_all) {
    int t = blockIdx.x;
    float s = 0.f;
    for (int i = threadIdx.x; i < B_ * F_; i += 256) {
        int b = i >> 7, f = i & 127;
        s += ev_all[(b * T_ + t) * F_ + f];
    }
    #pragma unroll
    for (int off = 16; off > 0; off >>= 1) s += __shfl_down_sync(0xffffffffu, s, off);
    __shared__ float rs[8];
    int lane = threadIdx.x & 31, w = threadIdx.x >> 5;
    if (lane == 0) rs[w] = s;
    __syncthreads();
    if (threadIdx.x == 0) {
        float tot = 0.f;
        #pragma unroll
        for (int i = 0; i < 8; i++) tot += rs[i];
        g_denom[t] = tot + 1e-8f;
    }
}

// ---------------- precompute GEMMs (gamma_h, alpha) ----------------
#define BM 32
#define BN 64
#define BK 32
__global__ __launch_bounds__(128) void k_gammah(const float* __restrict__ d_all,
                                                const float* __restrict__ W,
                                                const float* __restrict__ bias) {
    __shared__ float sA[BM][BK + 1];
    __shared__ float sB[BK][BN + 1];
    const int rr0 = blockIdx.y * BM;
    const int bn  = blockIdx.x * BN;
    const int tid = threadIdx.x;
    const int tr = tid >> 4, tc = tid & 15;
    float acc[4][4] = {};
    for (int k0 = 0; k0 < F_; k0 += BK) {
        #pragma unroll
        for (int i = tid; i < BM * BK; i += 128) {
            int r = i >> 5, kk = i & 31;
            int rr = rr0 + r;
            int b = rr & 255, tt = rr >> 8;
            sA[r][kk] = d_all[(b * T_ + tt) * F_ + k0 + kk];
        }
        #pragma unroll
        for (int i = tid; i < BK * BN; i += 128) {
            int nl = i >> 5, kk = i & 31;
            sB[kk][nl] = W[(bn + nl) * F_ + k0 + kk];
        }
        __syncthreads();
        #pragma unroll
        for (int kk = 0; kk < BK; kk++) {
            float a[4], bb[4];
            #pragma unroll
            for (int i = 0; i < 4; i++) a[i] = sA[tr * 4 + i][kk];
            #pragma unroll
            for (int j = 0; j < 4; j++) bb[j] = sB[kk][tc * 4 + j];
            #pragma unroll
            for (int i = 0; i < 4; i++)
                #pragma unroll
                for (int j = 0; j < 4; j++) acc[i][j] += a[i] * bb[j];
        }
        __syncthreads();
    }
    #pragma unroll
    for (int i = 0; i < 4; i++) {
        int rr = rr0 + tr * 4 + i;
        #pragma unroll
        for (int j = 0; j < 4; j++) {
            int n = bn + tc * 4 + j;
            float v = acc[i][j] + bias[n];
            g_gammah[rr * H_ + n] = expf(-fmaxf(v, 0.f));
        }
    }
}

__global__ __launch_bounds__(128) void k_alpha(const float* __restrict__ d_all,
                                               const float* __restrict__ m_all,
                                               const float* __restrict__ tdx_W,
                                               const float* __restrict__ tdx_b,
                                               const float* __restrict__ wc_W,
                                               const float* __restrict__ wc_b) {
    __shared__ float sA[BM][BK + 1];
    __shared__ float sB[BK][BN + 1];
    const int rr0 = blockIdx.y * BM;
    const int bn  = blockIdx.x * BN;
    const int tid = threadIdx.x;
    const int tr = tid >> 4, tc = tid & 15;
    float acc[4][4] = {};
    for (int k0 = 0; k0 < 2 * F_; k0 += BK) {
        #pragma unroll
        for (int i = tid; i < BM * BK; i += 128) {
            int r = i >> 5, kk = i & 31;
            int rr = rr0 + r;
            int b = rr & 255, tt = rr >> 8;
            int k = k0 + kk;
            float v;
            if (k < F_) {
                float dv = d_all[(b * T_ + tt) * F_ + k];
                float gv = dv * tdx_W[k * F_ + k] + tdx_b[k];
                v = expf(-fmaxf(gv, 0.f));
            } else {
                v = m_all[(b * T_ + tt) * F_ + (k - F_)];
            }
            sA[r][kk] = v;
        }
        #pragma unroll
        for (int i = tid; i < BK * BN; i += 128) {
            int nl = i >> 5, kk = i & 31;
            sB[kk][nl] = wc_W[(bn + nl) * 2 * F_ + k0 + kk];
        }
        __syncthreads();
        #pragma unroll
        for (int kk = 0; kk < BK; kk++) {
            float a[4], bb[4];
            #pragma unroll
            for (int i = 0; i < 4; i++) a[i] = sA[tr * 4 + i][kk];
            #pragma unroll
            for (int j = 0; j < 4; j++) bb[j] = sB[kk][tc * 4 + j];
            #pragma unroll
            for (int i = 0; i < 4; i++)
                #pragma unroll
                for (int j = 0; j < 4; j++) acc[i][j] += a[i] * bb[j];
        }
        __syncthreads();
    }
    #pragma unroll
    for (int i = 0; i < 4; i++) {
        int rr = rr0 + tr * 4 + i;
        #pragma unroll
        for (int j = 0; j < 4; j++) {
            int n = bn + tc * 4 + j;
            float s = acc[i][j] + wc_b[n];
            g_alpha[rr * F_ + n] = 1.f / (1.f + expf(-s));
        }
    }
}

// ---------------- grid barrier (all 128 blocks resident) ----------------
__device__ __forceinline__ void gbar(unsigned target) {
    __syncthreads();
    if (threadIdx.x == 0) {
        __threadfence();
        unsigned old = atomicAdd(&g_bar_count, 1u);
        if (old == GRID_MAIN - 1) {
            atomicExch(&g_bar_count, 0u);
            __threadfence();
            atomicExch(&g_gen, target);
        } else {
            while (*((volatile unsigned*)&g_gen) < target) { __nanosleep(64); }
        }
        __threadfence();
    }
    __syncthreads();
}

// smem layout (floats)
#define SW_W  (768 * 32)          // 24576: Ws[k][c], c = block's 32 gate cols
#define SW_A  (128 * 66)          // 8448:  As[r][kk], pitch 66 (bank-safe)
#define SW_X  64                  // bias[32] + red[8] + pad

__device__ __forceinline__ float sigf(float v) { return 1.f / (1.f + expf(-v)); }

// ---------------- the persistent main kernel ----------------
__global__ __launch_bounds__(THREADS_MAIN, 1) void k_main(
    const float* __restrict__ x_all, const float* __restrict__ m_all,
    const float* __restrict__ tx_all, const float* __restrict__ ev_all,
    const float* __restrict__ hist_W, const float* __restrict__ hist_b,
    const float* __restrict__ feat_b,
    const float* __restrict__ W_ih, const float* __restrict__ W_hh,
    const float* __restrict__ b_ih, const float* __restrict__ b_hh,
    float* __restrict__ out) {
    extern __shared__ float smem[];
    float* Ws    = smem;             // [768][32]
    float* As    = smem + SW_W;      // [128][66] (also reused as Gs[32][128], xs[2][128])
    float* extra = smem + SW_W + SW_A; // bias[32], red[8]

    const int tid = threadIdx.x;
    const int bi  = blockIdx.x;
    const int rh  = bi >> 6;          // row half (0/1)
    const int cs  = bi & 63;          // col slice (j group of 8)
    const int row0 = rh * 128;
    const int tr = tid >> 3;          // 0..31 -> 4 rows each
    const int tc = tid & 7;           // 0..7  -> 4 cols each

    // ---- one-time: load this block's weight slice + bias into smem ----
    for (int idx = tid; idx < 768 * 32; idx += THREADS_MAIN) {
        int k = idx >> 5, c = idx & 31;
        int gc = (c >> 3) * 512 + cs * 8 + (c & 7);
        Ws[k * 32 + c] = (k < 256) ? W_ih[gc * 256 + k] : W_hh[gc * 512 + (k - 256)];
    }
    if (tid < 32) {
        int gc = (tid >> 3) * 512 + cs * 8 + (tid & 7);
        extra[tid] = b_ih[gc] + b_hh[gc];
    }
    __syncthreads();

    unsigned bar = 0;

    for (int t = 0; t < T_; t++) {
        float acc[4][4] = {};
        float xacc = 0.f;
        const int xr  = tid & 127;      // x_hist: row within half
        const int xcl = tid >> 7;       // x_hist: which of block's 2 cols
        const int xcol = 2 * cs + xcl;

        // ============ phase 1: gates K-chunk 256..767 (A = hdec) + x_hist ============
        for (int k0 = 0; k0 < 512; k0 += 64) {
            // stage As[r][kk] <- hdec (cross-block data: bypass L1)
            for (int i = tid; i < 128 * 32; i += THREADS_MAIN) {
                int r = i >> 5, p = i & 31;
                float2 v = __ldcg((const float2*)&g_hdec[(row0 + r) * H_ + k0 + 2 * p]);
                *(float2*)&As[r * 66 + 2 * p] = v;
            }
            __syncthreads();
            const float* wsp = Ws + (256 + k0) * 32;
            #pragma unroll 8
            for (int kk = 0; kk < 64; kk += 2) {
                float2 a[4];
                #pragma unroll
                for (int i = 0; i < 4; i++)
                    a[i] = *(const float2*)&As[(tr * 4 + i) * 66 + kk];
                float4 w0 = *(const float4*)&wsp[kk * 32 + tc * 4];
                float4 w1 = *(const float4*)&wsp[(kk + 1) * 32 + tc * 4];
                #pragma unroll
                for (int i = 0; i < 4; i++) {
                    acc[i][0] += a[i].x * w0.x; acc[i][1] += a[i].x * w0.y;
                    acc[i][2] += a[i].x * w0.z; acc[i][3] += a[i].x * w0.w;
                    acc[i][0] += a[i].y * w1.x; acc[i][1] += a[i].y * w1.y;
                    acc[i][2] += a[i].y * w1.z; acc[i][3] += a[i].y * w1.w;
                }
            }
            // x_hist partial: reuse staged As tile
            {
                const float2* hw2 = (const float2*)(hist_W + xcol * H_ + k0);
                #pragma unroll 8
                for (int p = 0; p < 32; p++) {
                    float2 a = *(const float2*)&As[xr * 66 + 2 * p];
                    float2 w = __ldg(&hw2[p]);
                    xacc += a.x * w.x + a.y * w.y;
                }
            }
            __syncthreads();
        }
        // x_hist epilogue -> x_hist, x_c to global
        {
            float xh = xacc + hist_b[xcol];
            int b = row0 + xr;
            int base = (b * T_ + t) * F_ + xcol;
            float mv = m_all[base], xv = x_all[base];
            g_xhist[b * F_ + xcol] = xh;
            g_xc[b * F_ + xcol] = mv * xv + (1.f - mv) * xh;
        }
        gbar(++bar);

        // ============ phase 2: z_h + combine + cc + loss (2 rows per block) ============
        {
            const int s_ = tid >> 7, f = tid & 127;
            const int prow = bi * 2 + s_;
            float* xs = As;  // [2][128]
            xs[s_ * 128 + f] = __ldcg(&g_xc[prow * F_ + f]);
            __syncthreads();
            float z = feat_b[f];
            const float* xrow = xs + s_ * 128;
            #pragma unroll 8
            for (int k = 0; k < 128; k++) z += xrow[k] * g_featT[k * F_ + f];
            float xh = __ldcg(&g_xhist[prow * F_ + f]);
            float al = g_alpha[(t * B_ + prow) * F_ + f];
            int base = (prow * T_ + t) * F_ + f;
            float mv = m_all[base], xv = x_all[base];
            float ch = al * z + (1.f - al) * xh;
            float cc = mv * xv + (1.f - mv) * ch;
            g_cc[prow * F_ + f] = cc;
            out[base] = cc;
            float tg = tx_all[base], evv = ev_all[base];
            float e1 = xh - tg, e2 = z - tg, e3 = ch - tg;
            float l = evv * (e1 * e1 + e2 * e2 + e3 * e3);
            #pragma unroll
            for (int off = 16; off > 0; off >>= 1) l += __shfl_down_sync(0xffffffffu, l, off);
            float* red = extra + 32;
            int lane = tid & 31, w = tid >> 5;
            if (lane == 0) red[w] = l;
            __syncthreads();
            if (tid == 0) {
                float tot = 0.f;
                #pragma unroll
                for (int i = 0; i < 8; i++) tot += red[i];
                atomicAdd(&g_loss, (double)tot / ((double)g_denom[t] * (double)T_));
            }
        }
        gbar(++bar);

        // ============ phase 3: gates K-chunk 0..255 (A = [cc | m]) + LSTM ============
        for (int k0 = 0; k0 < 256; k0 += 64) {
            for (int i = tid; i < 128 * 32; i += THREADS_MAIN) {
                int r = i >> 5, p = i & 31;
                float2 v;
                if (k0 < 128)
                    v = __ldcg((const float2*)&g_cc[(row0 + r) * F_ + k0 + 2 * p]);
                else
                    v = *(const float2*)&m_all[((row0 + r) * T_ + t) * F_ + (k0 - 128) + 2 * p];
                *(float2*)&As[r * 66 + 2 * p] = v;
            }
            __syncthreads();
            const float* wsp = Ws + k0 * 32;
            #pragma unroll 8
            for (int kk = 0; kk < 64; kk += 2) {
                float2 a[4];
                #pragma unroll
                for (int i = 0; i < 4; i++)
                    a[i] = *(const float2*)&As[(tr * 4 + i) * 66 + kk];
                float4 w0 = *(const float4*)&wsp[kk * 32 + tc * 4];
                float4 w1 = *(const float4*)&wsp[(kk + 1) * 32 + tc * 4];
                #pragma unroll
                for (int i = 0; i < 4; i++) {
                    acc[i][0] += a[i].x * w0.x; acc[i][1] += a[i].x * w0.y;
                    acc[i][2] += a[i].x * w0.z; acc[i][3] += a[i].x * w0.w;
                    acc[i][0] += a[i].y * w1.x; acc[i][1] += a[i].y * w1.y;
                    acc[i][2] += a[i].y * w1.z; acc[i][3] += a[i].y * w1.w;
                }
            }
            __syncthreads();
        }
        // gates -> smem Gs[c][r] (with bias), then LSTM on block-local cells
        {
            float* Gs = As;  // [32][128]
            #pragma unroll
            for (int j = 0; j < 4; j++) {
                float bj = extra[tc * 4 + j];
                #pragma unroll
                for (int i = 0; i < 4; i++)
                    Gs[(tc * 4 + j) * 128 + (tr * 4 + i)] = acc[i][j] + bj;
            }
            __syncthreads();
            #pragma unroll
            for (int u = 0; u < 4; u++) {
                int id = tid * 4 + u;
                int r = id >> 3, jo = id & 7;
                float ig = Gs[(0 * 8 + jo) * 128 + r];
                float fg = Gs[(1 * 8 + jo) * 128 + r];
                float gg = Gs[(2 * 8 + jo) * 128 + r];
                float og = Gs[(3 * 8 + jo) * 128 + r];
                int b = row0 + r, j = cs * 8 + jo;
                float cold = g_c[b * H_ + j];
                float cn = sigf(fg) * cold + sigf(ig) * tanhf(gg);
                g_c[b * H_ + j] = cn;
                float h = sigf(og) * tanhf(cn);
                if (t < T_ - 1)
                    g_hdec[b * H_ + j] = h * g_gammah[((t + 1) * B_ + b) * H_ + j];
            }
        }
        gbar(++bar);
    }
}

// ---------------- finalize ----------------
__global__ void k_finish(float* __restrict__ out, int out_size) {
    out[out_size - 1] = (float)g_loss;
}

// ---------------- launch ----------------
extern "C" void kernel_launch(void* const* d_in, const int* in_sizes, int n_in,
                              void* d_out, int out_size) {
    const float* x      = (const float*)d_in[0];
    const float* m      = (const float*)d_in[1];
    const float* d      = (const float*)d_in[2];
    const float* tx     = (const float*)d_in[3];
    const float* ev     = (const float*)d_in[4];
    const float* td_h_W = (const float*)d_in[5];
    const float* td_h_b = (const float*)d_in[6];
    const float* td_x_W = (const float*)d_in[7];
    const float* td_x_b = (const float*)d_in[8];
    const float* hist_W = (const float*)d_in[9];
    const float* hist_b = (const float*)d_in[10];
    const float* feat_W = (const float*)d_in[11];
    const float* feat_b = (const float*)d_in[12];
    const float* wc_W   = (const float*)d_in[13];
    const float* wc_b   = (const float*)d_in[14];
    const float* W_ih   = (const float*)d_in[15];
    const float* W_hh   = (const float*)d_in[16];
    const float* b_ih   = (const float*)d_in[17];
    const float* b_hh   = (const float*)d_in[18];
    float* out = (float*)d_out;

    static int smem_set = 0;
    size_t smem_bytes = (size_t)(SW_W + SW_A + SW_X) * sizeof(float);
    if (!smem_set) {
        cudaFuncSetAttribute(k_main, cudaFuncAttributeMaxDynamicSharedMemorySize,
                             (int)smem_bytes);
        smem_set = 1;
    }

    k_init<<<512, 256>>>(feat_W);
    k_denom<<<T_, 256>>>(ev);
    k_gammah<<<dim3(H_ / BN, (T_ * B_) / BM), 128>>>(d, td_h_W, td_h_b);
    k_alpha<<<dim3(F_ / BN, (T_ * B_) / BM), 128>>>(d, m, td_x_W, td_x_b, wc_W, wc_b);
    k_main<<<GRID_MAIN, THREADS_MAIN, smem_bytes>>>(
        x, m, tx, ev, hist_W, hist_b, feat_b, W_ih, W_hh, b_ih, b_hh, out);
    k_finish<<<1, 1>>>(out, out_size);
}

// round 3
// speedup vs baseline: 2.1915x; 1.1185x over previous
#include <cuda_runtime.h>
#include <math.h>

// Problem dims
#define B_  256
#define T_  128
#define F_  128
#define H_  512
#define GRID_MAIN 128
#define THREADS_MAIN 256

// ---------------- persistent device state / scratch ----------------
__device__ float  g_gammah[T_ * B_ * H_];   // [t][b][j]
__device__ float  g_alpha [T_ * B_ * F_];   // [t][b][f]
__device__ float  g_hdec [B_ * H_];         // h * gamma_h[t]
__device__ float  g_cc   [B_ * F_];
__device__ float  g_featT[F_ * F_];         // featT[k][f] = feat_W[f][k], diag zeroed
__device__ float  g_histT[H_ * F_];         // histT[k][f] = hist_W[f][k]
__device__ float  g_denom[T_];
__device__ double g_loss;
__device__ unsigned g_flags[GRID_MAIN * 8]; // one flag per block, 32B apart

// ---------------- init ----------------
__global__ void k_init(const float* __restrict__ feat_W, const float* __restrict__ hist_W) {
    int idx = blockIdx.x * blockDim.x + threadIdx.x;   // 131072 threads
    if (idx < B_ * H_) g_hdec[idx] = 0.f;
    if (idx == 0) g_loss = 0.0;
    if (idx < GRID_MAIN * 8) g_flags[idx] = 0u;
    if (idx < F_ * F_) {
        int k = idx >> 7, f = idx & 127;
        g_featT[idx] = (f == k) ? 0.f : feat_W[f * F_ + k];
    }
    if (idx < H_ * F_) {
        int k = idx >> 7, f = idx & 127;
        g_histT[idx] = hist_W[f * H_ + k];
    }
}

// ---------------- denom[t] ----------------
__global__ void k_denom(const float* __restrict__ ev_all) {
    int t = blockIdx.x;
    float s = 0.f;
    for (int i = threadIdx.x; i < B_ * F_; i += 256) {
        int b = i >> 7, f = i & 127;
        s += ev_all[(b * T_ + t) * F_ + f];
    }
    #pragma unroll
    for (int off = 16; off > 0; off >>= 1) s += __shfl_down_sync(0xffffffffu, s, off);
    __shared__ float rs[8];
    int lane = threadIdx.x & 31, w = threadIdx.x >> 5;
    if (lane == 0) rs[w] = s;
    __syncthreads();
    if (threadIdx.x == 0) {
        float tot = 0.f;
        #pragma unroll
        for (int i = 0; i < 8; i++) tot += rs[i];
        g_denom[t] = tot + 1e-8f;
    }
}

// ---------------- precompute GEMMs: 64x64 tiles, 256 threads ----------------
#define PBM 64
#define PBN 64
#define PBK 32
__global__ __launch_bounds__(256) void k_gammah(const float* __restrict__ d_all,
                                                const float* __restrict__ W,
                                                const float* __restrict__ bias) {
    __shared__ float sA[PBM][PBK + 1];
    __shared__ float sB[PBK][PBN + 1];
    const int rr0 = blockIdx.y * PBM;
    const int bn  = blockIdx.x * PBN;
    const int tid = threadIdx.x;
    const int tr = tid >> 4, tc = tid & 15;
    float acc[4][4] = {};
    for (int k0 = 0; k0 < F_; k0 += PBK) {
        #pragma unroll
        for (int i = tid; i < PBM * PBK; i += 256) {
            int r = i >> 5, kk = i & 31;
            int rr = rr0 + r;
            int b = rr & 255, tt = rr >> 8;
            sA[r][kk] = d_all[(b * T_ + tt) * F_ + k0 + kk];
        }
        #pragma unroll
        for (int i = tid; i < PBK * PBN; i += 256) {
            int nl = i >> 5, kk = i & 31;
            sB[kk][nl] = W[(bn + nl) * F_ + k0 + kk];
        }
        __syncthreads();
        #pragma unroll
        for (int kk = 0; kk < PBK; kk++) {
            float a[4], bb[4];
            #pragma unroll
            for (int i = 0; i < 4; i++) a[i] = sA[tr * 4 + i][kk];
            #pragma unroll
            for (int j = 0; j < 4; j++) bb[j] = sB[kk][tc * 4 + j];
            #pragma unroll
            for (int i = 0; i < 4; i++)
                #pragma unroll
                for (int j = 0; j < 4; j++) acc[i][j] += a[i] * bb[j];
        }
        __syncthreads();
    }
    #pragma unroll
    for (int i = 0; i < 4; i++) {
        int rr = rr0 + tr * 4 + i;
        #pragma unroll
        for (int j = 0; j < 4; j++) {
            int n = bn + tc * 4 + j;
            float v = acc[i][j] + bias[n];
            g_gammah[rr * H_ + n] = expf(-fmaxf(v, 0.f));
        }
    }
}

__global__ __launch_bounds__(256) void k_alpha(const float* __restrict__ d_all,
                                               const float* __restrict__ m_all,
                                               const float* __restrict__ tdx_W,
                                               const float* __restrict__ tdx_b,
                                               const float* __restrict__ wc_W,
                                               const float* __restrict__ wc_b) {
    __shared__ float sA[PBM][PBK + 1];
    __shared__ float sB[PBK][PBN + 1];
    const int rr0 = blockIdx.y * PBM;
    const int bn  = blockIdx.x * PBN;
    const int tid = threadIdx.x;
    const int tr = tid >> 4, tc = tid & 15;
    float acc[4][4] = {};
    for (int k0 = 0; k0 < 2 * F_; k0 += PBK) {
        #pragma unroll
        for (int i = tid; i < PBM * PBK; i += 256) {
            int r = i >> 5, kk = i & 31;
            int rr = rr0 + r;
            int b = rr & 255, tt = rr >> 8;
            int k = k0 + kk;
            float v;
            if (k < F_) {
                float dv = d_all[(b * T_ + tt) * F_ + k];
                float gv = dv * tdx_W[k * F_ + k] + tdx_b[k];
                v = expf(-fmaxf(gv, 0.f));
            } else {
                v = m_all[(b * T_ + tt) * F_ + (k - F_)];
            }
            sA[r][kk] = v;
        }
        #pragma unroll
        for (int i = tid; i < PBK * PBN; i += 256) {
            int nl = i >> 5, kk = i & 31;
            sB[kk][nl] = wc_W[(bn + nl) * 2 * F_ + k0 + kk];
        }
        __syncthreads();
        #pragma unroll
        for (int kk = 0; kk < PBK; kk++) {
            float a[4], bb[4];
            #pragma unroll
            for (int i = 0; i < 4; i++) a[i] = sA[tr * 4 + i][kk];
            #pragma unroll
            for (int j = 0; j < 4; j++) bb[j] = sB[kk][tc * 4 + j];
            #pragma unroll
            for (int i = 0; i < 4; i++)
                #pragma unroll
                for (int j = 0; j < 4; j++) acc[i][j] += a[i] * bb[j];
        }
        __syncthreads();
    }
    #pragma unroll
    for (int i = 0; i < 4; i++) {
        int rr = rr0 + tr * 4 + i;
        #pragma unroll
        for (int j = 0; j < 4; j++) {
            int n = bn + tc * 4 + j;
            float s = acc[i][j] + wc_b[n];
            g_alpha[rr * F_ + n] = 1.f / (1.f + expf(-s));
        }
    }
}

// ---------------- cp.async helpers ----------------
__device__ __forceinline__ void cpasync16(float* smem_dst, const float* gsrc) {
    unsigned sa = (unsigned)__cvta_generic_to_shared(smem_dst);
    asm volatile("cp.async.cg.shared.global [%0], [%1], 16;\n" :: "r"(sa), "l"(gsrc) : "memory");
}
__device__ __forceinline__ void cp_commit() { asm volatile("cp.async.commit_group;\n" ::: "memory"); }
__device__ __forceinline__ void cp_wait1()  { asm volatile("cp.async.wait_group 1;\n" ::: "memory"); }
__device__ __forceinline__ void cp_wait0()  { asm volatile("cp.async.wait_group 0;\n" ::: "memory"); }

// ---------------- distributed-flag grid barrier ----------------
__device__ __forceinline__ void gbar(unsigned target) {
    __syncthreads();
    if (threadIdx.x == 0) {
        __threadfence();
        atomicExch(&g_flags[blockIdx.x * 8], target);
    }
    if (threadIdx.x < GRID_MAIN) {
        const volatile unsigned* fl = (const volatile unsigned*)&g_flags[threadIdx.x * 8];
        while (*fl < target) { __nanosleep(32); }
    }
    __syncthreads();
    __threadfence();
}

// smem layout (floats)
#define AS_PITCH 68                 // 272B rows, 16B-aligned
#define SW_W   (768 * 32)           // 24576
#define SW_A   (128 * AS_PITCH)     // 8704 per buffer
#define SMEM_FLOATS (SW_W + 2 * SW_A + 64)

__device__ __forceinline__ float sigf(float v) { return 1.f / (1.f + expf(-v)); }

// 64-k GEMM chunk: As[128][AS_PITCH] x Ws-slice[64][32] -> acc[4][4]
__device__ __forceinline__ void gemm_chunk(const float* __restrict__ Asb,
                                           const float* __restrict__ wsp,
                                           float acc[4][4], int tr, int tc) {
    #pragma unroll 8
    for (int kk = 0; kk < 64; kk += 4) {
        float4 a0 = *(const float4*)&Asb[(tr * 4 + 0) * AS_PITCH + kk];
        float4 a1 = *(const float4*)&Asb[(tr * 4 + 1) * AS_PITCH + kk];
        float4 a2 = *(const float4*)&Asb[(tr * 4 + 2) * AS_PITCH + kk];
        float4 a3 = *(const float4*)&Asb[(tr * 4 + 3) * AS_PITCH + kk];
        #define DOK(Q, C) { \
            float4 w = *(const float4*)&wsp[(kk + Q) * 32 + tc * 4]; \
            acc[0][0] += a0.C * w.x; acc[0][1] += a0.C * w.y; acc[0][2] += a0.C * w.z; acc[0][3] += a0.C * w.w; \
            acc[1][0] += a1.C * w.x; acc[1][1] += a1.C * w.y; acc[1][2] += a1.C * w.z; acc[1][3] += a1.C * w.w; \
            acc[2][0] += a2.C * w.x; acc[2][1] += a2.C * w.y; acc[2][2] += a2.C * w.z; acc[2][3] += a2.C * w.w; \
            acc[3][0] += a3.C * w.x; acc[3][1] += a3.C * w.y; acc[3][2] += a3.C * w.z; acc[3][3] += a3.C * w.w; }
        DOK(0, x) DOK(1, y) DOK(2, z) DOK(3, w)
        #undef DOK
    }
}

// ---------------- the persistent main kernel ----------------
__global__ __launch_bounds__(THREADS_MAIN, 1) void k_main(
    const float* __restrict__ x_all, const float* __restrict__ m_all,
    const float* __restrict__ tx_all, const float* __restrict__ ev_all,
    const float* __restrict__ hist_b, const float* __restrict__ feat_b,
    const float* __restrict__ W_ih, const float* __restrict__ W_hh,
    const float* __restrict__ b_ih, const float* __restrict__ b_hh,
    float* __restrict__ out) {
    extern __shared__ float smem[];
    float* Ws    = smem;                    // [768][32]
    float* As0   = smem + SW_W;
    float* As1   = As0 + SW_A;
    float* extra = As1 + SW_A;              // bias[32], red[8]

    const int tid = threadIdx.x;
    const int bi  = blockIdx.x;
    const int rh  = bi >> 6;                // row half
    const int cs  = bi & 63;                // col slice (8 j's)
    const int row0 = rh * 128;
    const int tr = tid >> 3;                // 0..31 -> 4 rows
    const int tc = tid & 7;                 // 0..7  -> 4 cols
    const int rr = tid >> 7;                // epilogue row select (0/1)
    const int f  = tid & 127;               // epilogue feature
    const int prow = bi * 2 + rr;           // this thread's owned row
    const int rloc = (cs) * 2 + rr;         // local row in staged half
    float* Asbuf[2] = { As0, As1 };

    // ---- one-time: weight slice + bias ----
    for (int idx = tid; idx < 768 * 32; idx += THREADS_MAIN) {
        int k = idx >> 5, c = idx & 31;
        int gc = (c >> 3) * 512 + cs * 8 + (c & 7);
        Ws[k * 32 + c] = (k < 256) ? W_ih[gc * 256 + k] : W_hh[gc * 512 + (k - 256)];
    }
    if (tid < 32) {
        int gc = (tid >> 3) * 512 + cs * 8 + (tid & 7);
        extra[tid] = b_ih[gc] + b_hh[gc];
    }
    __syncthreads();

    float cstate[4] = {0.f, 0.f, 0.f, 0.f};
    unsigned bar = 0;

    for (int t = 0; t < T_; t++) {
        float acc[4][4] = {};
        float xacc = 0.f;

        // ============ phase 1: gates K 256..767 (A = hdec) + row-local x_hist ============
        // stage chunk 0
        for (int i = tid; i < 2048; i += THREADS_MAIN) {
            int r = i >> 4, p = i & 15;
            cpasync16(&As0[r * AS_PITCH + p * 4], &g_hdec[(row0 + r) * H_ + p * 4]);
        }
        cp_commit();
        for (int c = 0; c < 8; c++) {
            if (c + 1 < 8) {
                int k0n = (c + 1) * 64;
                float* dstb = Asbuf[(c + 1) & 1];
                for (int i = tid; i < 2048; i += THREADS_MAIN) {
                    int r = i >> 4, p = i & 15;
                    cpasync16(&dstb[r * AS_PITCH + p * 4], &g_hdec[(row0 + r) * H_ + k0n + p * 4]);
                }
                cp_commit();
                cp_wait1();
            } else {
                cp_wait0();
            }
            __syncthreads();
            const float* Asb = Asbuf[c & 1];
            gemm_chunk(Asb, Ws + (256 + c * 64) * 32, acc, tr, tc);
            // x_hist partial for owned row
            {
                const float* ar = Asb + rloc * AS_PITCH;
                const float* hp = g_histT + (c * 64) * F_ + f;
                #pragma unroll 4
                for (int kk = 0; kk < 64; kk += 4) {
                    float4 a = *(const float4*)&ar[kk];
                    xacc += a.x * hp[(kk    ) * F_] + a.y * hp[(kk + 1) * F_]
                          + a.z * hp[(kk + 2) * F_] + a.w * hp[(kk + 3) * F_];
                }
            }
            __syncthreads();
        }
        // ---- row-local chain: x_hist -> x_c -> z_h -> c_h -> cc -> loss ----
        {
            float xh = xacc + hist_b[f];
            int base = (prow * T_ + t) * F_ + f;
            float mv = m_all[base], xv = x_all[base];
            float xc = mv * xv + (1.f - mv) * xh;
            float* xs = As0;   // free now
            xs[rr * 128 + f] = xc;
            __syncthreads();
            float z = feat_b[f];
            const float* xrow = xs + rr * 128;
            #pragma unroll 8
            for (int k = 0; k < 128; k++) z += xrow[k] * g_featT[k * F_ + f];
            float al = g_alpha[(t * B_ + prow) * F_ + f];
            float ch = al * z + (1.f - al) * xh;
            float cc = mv * xv + (1.f - mv) * ch;
            __stcg(&g_cc[prow * F_ + f], cc);
            out[base] = cc;
            float tg = tx_all[base], evv = ev_all[base];
            float e1 = xh - tg, e2 = z - tg, e3 = ch - tg;
            float l = evv * (e1 * e1 + e2 * e2 + e3 * e3);
            #pragma unroll
            for (int off = 16; off > 0; off >>= 1) l += __shfl_down_sync(0xffffffffu, l, off);
            float* red = extra + 32;
            int lane = tid & 31, w = tid >> 5;
            if (lane == 0) red[w] = l;
            __syncthreads();
            if (tid == 0) {
                float tot = 0.f;
                #pragma unroll
                for (int i = 0; i < 8; i++) tot += red[i];
                atomicAdd(&g_loss, (double)tot / ((double)g_denom[t] * (double)T_));
            }
        }
        gbar(++bar);

        // ============ phase 3: gates K 0..255 (A = [cc | m]) + LSTM ============
        for (int i = tid; i < 2048; i += THREADS_MAIN) {
            int r = i >> 4, p = i & 15;
            cpasync16(&As0[r * AS_PITCH + p * 4], &g_cc[(row0 + r) * F_ + p * 4]);
        }
        cp_commit();
        for (int c = 0; c < 4; c++) {
            if (c + 1 < 4) {
                int k0n = (c + 1) * 64;
                float* dstb = Asbuf[(c + 1) & 1];
                for (int i = tid; i < 2048; i += THREADS_MAIN) {
                    int r = i >> 4, p = i & 15;
                    const float* src = (k0n < 128)
                        ? &g_cc[(row0 + r) * F_ + k0n + p * 4]
                        : &m_all[((row0 + r) * T_ + t) * F_ + (k0n - 128) + p * 4];
                    cpasync16(&dstb[r * AS_PITCH + p * 4], src);
                }
                cp_commit();
                cp_wait1();
            } else {
                cp_wait0();
            }
            __syncthreads();
            gemm_chunk(Asbuf[c & 1], Ws + (c * 64) * 32, acc, tr, tc);
            __syncthreads();
        }
        // gates -> smem transpose, LSTM with register-resident c-state
        {
            float* Gs = As0;   // [32][128]
            #pragma unroll
            for (int j = 0; j < 4; j++) {
                float bj = extra[tc * 4 + j];
                #pragma unroll
                for (int i = 0; i < 4; i++)
                    Gs[(tc * 4 + j) * 128 + (tr * 4 + i)] = acc[i][j] + bj;
            }
            __syncthreads();
            #pragma unroll
            for (int u = 0; u < 4; u++) {
                int id = tid * 4 + u;
                int r = id >> 3, jo = id & 7;
                float ig = Gs[(0 * 8 + jo) * 128 + r];
                float fg = Gs[(1 * 8 + jo) * 128 + r];
                float gg = Gs[(2 * 8 + jo) * 128 + r];
                float og = Gs[(3 * 8 + jo) * 128 + r];
                float cn = sigf(fg) * cstate[u] + sigf(ig) * tanhf(gg);
                cstate[u] = cn;
                float h = sigf(og) * tanhf(cn);
                if (t < T_ - 1) {
                    int b = row0 + r, j = cs * 8 + jo;
                    __stcg(&g_hdec[b * H_ + j], h * g_gammah[((t + 1) * B_ + b) * H_ + j]);
                }
            }
        }
        if (t < T_ - 1) gbar(++bar);
    }
}

// ---------------- finalize ----------------
__global__ void k_finish(float* __restrict__ out, int out_size) {
    out[out_size - 1] = (float)g_loss;
}

// ---------------- launch ----------------
extern "C" void kernel_launch(void* const* d_in, const int* in_sizes, int n_in,
                              void* d_out, int out_size) {
    const float* x      = (const float*)d_in[0];
    const float* m      = (const float*)d_in[1];
    const float* d      = (const float*)d_in[2];
    const float* tx     = (const float*)d_in[3];
    const float* ev     = (const float*)d_in[4];
    const float* td_h_W = (const float*)d_in[5];
    const float* td_h_b = (const float*)d_in[6];
    const float* td_x_W = (const float*)d_in[7];
    const float* td_x_b = (const float*)d_in[8];
    const float* hist_W = (const float*)d_in[9];
    const float* hist_b = (const float*)d_in[10];
    const float* feat_W = (const float*)d_in[11];
    const float* feat_b = (const float*)d_in[12];
    const float* wc_W   = (const float*)d_in[13];
    const float* wc_b   = (const float*)d_in[14];
    const float* W_ih   = (const float*)d_in[15];
    const float* W_hh   = (const float*)d_in[16];
    const float* b_ih   = (const float*)d_in[17];
    const float* b_hh   = (const float*)d_in[18];
    float* out = (float*)d_out;

    static int smem_set = 0;
    size_t smem_bytes = (size_t)SMEM_FLOATS * sizeof(float);
    if (!smem_set) {
        cudaFuncSetAttribute(k_main, cudaFuncAttributeMaxDynamicSharedMemorySize,
                             (int)smem_bytes);
        smem_set = 1;
    }

    k_init<<<512, 256>>>(feat_W, hist_W);
    k_denom<<<T_, 256>>>(ev);
    k_gammah<<<dim3(H_ / PBN, (T_ * B_) / PBM), 256>>>(d, td_h_W, td_h_b);
    k_alpha<<<dim3(F_ / PBN, (T_ * B_) / PBM), 256>>>(d, m, td_x_W, td_x_b, wc_W, wc_b);
    k_main<<<GRID_MAIN, THREADS_MAIN, smem_bytes>>>(
        x, m, tx, ev, hist_b, feat_b, W_ih, W_hh, b_ih, b_hh, out);
    k_finish<<<1, 1>>>(out, out_size);
}

// round 5
// speedup vs baseline: 4.3242x; 1.9731x over previous
#include <cuda_runtime.h>
#include <cuda_bf16.h>
#include <math.h>
#include <stdint.h>

// Problem dims
#define B_  256
#define T_  128
#define F_  128
#define H_  512
#define NCOMB 2176          // 2048 permuted gate cols + 128 hist cols
#define GRID_MAIN 136       // 4 row-groups x 34 col-tiles
#define THREADS_MAIN 256

// ---------------- persistent device state / scratch ----------------
__device__ float          g_gammah[T_ * B_ * H_];   // [t][b][j]
__device__ float          g_alpha [T_ * B_ * F_];   // [t][b][f]
__device__ __nv_bfloat16  g_hd16hi[B_ * H_];
__device__ __nv_bfloat16  g_hd16lo[B_ * H_];
__device__ __nv_bfloat16  g_cc16hi[B_ * F_];
__device__ __nv_bfloat16  g_cc16lo[B_ * F_];
__device__ __nv_bfloat16  g_m16   [B_ * T_ * F_];
__device__ __nv_bfloat16  g_Bhi   [NCOMB * 768];    // [n'][k], gate cols permuted
__device__ __nv_bfloat16  g_Blo   [NCOMB * 768];
__device__ float          g_biasp [2048];           // permuted b_ih + b_hh
__device__ float          g_xhist [B_ * F_];        // includes hist_b
__device__ float          g_featT [F_ * F_];        // featT[k][f], diag zeroed
__device__ float          g_denom [T_];
__device__ double         g_loss;
__device__ unsigned       g_flags [GRID_MAIN * 8];

__device__ __forceinline__ float sigf(float v) { return 1.f / (1.f + expf(-v)); }

// ---------------- mma / ldmatrix helpers (base-arch, NOT tcgen05) ----------------
__device__ __forceinline__ void ldsm_x4(uint32_t* r, unsigned addr) {
    asm volatile("ldmatrix.sync.aligned.m8n8.x4.shared.b16 {%0,%1,%2,%3}, [%4];"
                 : "=r"(r[0]), "=r"(r[1]), "=r"(r[2]), "=r"(r[3]) : "r"(addr));
}
__device__ __forceinline__ void ldsm_x2(uint32_t* r, unsigned addr) {
    asm volatile("ldmatrix.sync.aligned.m8n8.x2.shared.b16 {%0,%1}, [%2];"
                 : "=r"(r[0]), "=r"(r[1]) : "r"(addr));
}
__device__ __forceinline__ void mma16816(float* d, const uint32_t* a, const uint32_t* b) {
    asm volatile("mma.sync.aligned.m16n8k16.row.col.f32.bf16.bf16.f32 "
                 "{%0,%1,%2,%3}, {%4,%5,%6,%7}, {%8,%9}, {%0,%1,%2,%3};"
                 : "+f"(d[0]), "+f"(d[1]), "+f"(d[2]), "+f"(d[3])
                 : "r"(a[0]), "r"(a[1]), "r"(a[2]), "r"(a[3]), "r"(b[0]), "r"(b[1]));
}
__device__ __forceinline__ void cpa16(unsigned dst, const void* src) {
    asm volatile("cp.async.cg.shared.global [%0], [%1], 16;" :: "r"(dst), "l"(src) : "memory");
}
__device__ __forceinline__ void cp_commit() { asm volatile("cp.async.commit_group;" ::: "memory"); }
__device__ __forceinline__ void cp_wait1()  { asm volatile("cp.async.wait_group 1;" ::: "memory"); }
__device__ __forceinline__ void cp_wait0()  { asm volatile("cp.async.wait_group 0;" ::: "memory"); }

// ---------------- init ----------------
__global__ void k_init(const float* __restrict__ feat_W) {
    int idx = blockIdx.x * blockDim.x + threadIdx.x;   // 131072 threads
    if (idx < B_ * H_) {
        g_hd16hi[idx] = __float2bfloat16(0.f);
        g_hd16lo[idx] = __float2bfloat16(0.f);
    }
    if (idx == 0) g_loss = 0.0;
    if (idx < GRID_MAIN * 8) g_flags[idx] = 0u;
    if (idx < F_ * F_) {
        int k = idx >> 7, f = idx & 127;
        g_featT[idx] = (f == k) ? 0.f : feat_W[f * F_ + k];
    }
}

// ---------------- weight split (permuted) + m bf16 + bias ----------------
__global__ void k_prep(const float* __restrict__ W_ih, const float* __restrict__ W_hh,
                       const float* __restrict__ hist_W,
                       const float* __restrict__ b_ih, const float* __restrict__ b_hh,
                       const float* __restrict__ m_all) {
    int stride = gridDim.x * blockDim.x;
    int tid0 = blockIdx.x * blockDim.x + threadIdx.x;
    for (int idx = tid0; idx < NCOMB * 768; idx += stride) {
        int np = idx / 768, k = idx - np * 768;
        float w;
        if (np < 2048) {
            int ct = np >> 6, c = np & 63;
            int n = (c >> 4) * 512 + (ct << 4) + (c & 15);   // gate-interleaved permute
            w = (k < 256) ? W_ih[n * 256 + k] : W_hh[n * 512 + (k - 256)];
        } else {
            int f = np - 2048;
            w = (k < 256) ? 0.f : hist_W[f * 512 + (k - 256)];
        }
        __nv_bfloat16 hi = __float2bfloat16(w);
        g_Bhi[idx] = hi;
        g_Blo[idx] = __float2bfloat16(w - __bfloat162float(hi));
    }
    for (int idx = tid0; idx < B_ * T_ * F_; idx += stride)
        g_m16[idx] = __float2bfloat16(m_all[idx]);
    for (int idx = tid0; idx < 2048; idx += stride) {
        int ct = idx >> 6, c = idx & 63;
        int n = (c >> 4) * 512 + (ct << 4) + (c & 15);
        g_biasp[idx] = b_ih[n] + b_hh[n];
    }
}

// ---------------- denom[t] ----------------
__global__ void k_denom(const float* __restrict__ ev_all) {
    int t = blockIdx.x;
    float s = 0.f;
    for (int i = threadIdx.x; i < B_ * F_; i += 256) {
        int b = i >> 7, f = i & 127;
        s += ev_all[(b * T_ + t) * F_ + f];
    }
    #pragma unroll
    for (int off = 16; off > 0; off >>= 1) s += __shfl_down_sync(0xffffffffu, s, off);
    __shared__ float rs[8];
    int lane = threadIdx.x & 31, w = threadIdx.x >> 5;
    if (lane == 0) rs[w] = s;
    __syncthreads();
    if (threadIdx.x == 0) {
        float tot = 0.f;
        #pragma unroll
        for (int i = 0; i < 8; i++) tot += rs[i];
        g_denom[t] = tot + 1e-8f;
    }
}

// ---------------- precompute GEMMs (fp32 SIMT, parallel over T) ----------------
#define PBM 64
#define PBN 64
#define PBK 32
__global__ __launch_bounds__(256) void k_gammah(const float* __restrict__ d_all,
                                                const float* __restrict__ W,
                                                const float* __restrict__ bias) {
    __shared__ float sA[PBM][PBK + 1];
    __shared__ float sB[PBK][PBN + 1];
    const int rr0 = blockIdx.y * PBM;
    const int bn  = blockIdx.x * PBN;
    const int tid = threadIdx.x;
    const int tr = tid >> 4, tc = tid & 15;
    float acc[4][4] = {};
    for (int k0 = 0; k0 < F_; k0 += PBK) {
        #pragma unroll
        for (int i = tid; i < PBM * PBK; i += 256) {
            int r = i >> 5, kk = i & 31;
            int rr = rr0 + r;
            int b = rr & 255, tt = rr >> 8;
            sA[r][kk] = d_all[(b * T_ + tt) * F_ + k0 + kk];
        }
        #pragma unroll
        for (int i = tid; i < PBK * PBN; i += 256) {
            int nl = i >> 5, kk = i & 31;
            sB[kk][nl] = W[(bn + nl) * F_ + k0 + kk];
        }
        __syncthreads();
        #pragma unroll
        for (int kk = 0; kk < PBK; kk++) {
            float a[4], bb[4];
            #pragma unroll
            for (int i = 0; i < 4; i++) a[i] = sA[tr * 4 + i][kk];
            #pragma unroll
            for (int j = 0; j < 4; j++) bb[j] = sB[kk][tc * 4 + j];
            #pragma unroll
            for (int i = 0; i < 4; i++)
                #pragma unroll
                for (int j = 0; j < 4; j++) acc[i][j] += a[i] * bb[j];
        }
        __syncthreads();
    }
    #pragma unroll
    for (int i = 0; i < 4; i++) {
        int rr = rr0 + tr * 4 + i;
        #pragma unroll
        for (int j = 0; j < 4; j++) {
            int n = bn + tc * 4 + j;
            float v = acc[i][j] + bias[n];
            g_gammah[(size_t)rr * H_ + n] = expf(-fmaxf(v, 0.f));
        }
    }
}

__global__ __launch_bounds__(256) void k_alpha(const float* __restrict__ d_all,
                                               const float* __restrict__ m_all,
                                               const float* __restrict__ tdx_W,
                                               const float* __restrict__ tdx_b,
                                               const float* __restrict__ wc_W,
                                               const float* __restrict__ wc_b) {
    __shared__ float sA[PBM][PBK + 1];
    __shared__ float sB[PBK][PBN + 1];
    const int rr0 = blockIdx.y * PBM;
    const int bn  = blockIdx.x * PBN;
    const int tid = threadIdx.x;
    const int tr = tid >> 4, tc = tid & 15;
    float acc[4][4] = {};
    for (int k0 = 0; k0 < 2 * F_; k0 += PBK) {
        #pragma unroll
        for (int i = tid; i < PBM * PBK; i += 256) {
            int r = i >> 5, kk = i & 31;
            int rr = rr0 + r;
            int b = rr & 255, tt = rr >> 8;
            int k = k0 + kk;
            float v;
            if (k < F_) {
                float dv = d_all[(b * T_ + tt) * F_ + k];
                float gv = dv * tdx_W[k * F_ + k] + tdx_b[k];
                v = expf(-fmaxf(gv, 0.f));
            } else {
                v = m_all[(b * T_ + tt) * F_ + (k - F_)];
            }
            sA[r][kk] = v;
        }
        #pragma unroll
        for (int i = tid; i < PBK * PBN; i += 256) {
            int nl = i >> 5, kk = i & 31;
            sB[kk][nl] = wc_W[(bn + nl) * 2 * F_ + k0 + kk];
        }
        __syncthreads();
        #pragma unroll
        for (int kk = 0; kk < PBK; kk++) {
            float a[4], bb[4];
            #pragma unroll
            for (int i = 0; i < 4; i++) a[i] = sA[tr * 4 + i][kk];
            #pragma unroll
            for (int j = 0; j < 4; j++) bb[j] = sB[kk][tc * 4 + j];
            #pragma unroll
            for (int i = 0; i < 4; i++)
                #pragma unroll
                for (int j = 0; j < 4; j++) acc[i][j] += a[i] * bb[j];
        }
        __syncthreads();
    }
    #pragma unroll
    for (int i = 0; i < 4; i++) {
        int rr = rr0 + tr * 4 + i;
        #pragma unroll
        for (int j = 0; j < 4; j++) {
            int n = bn + tc * 4 + j;
            float s = acc[i][j] + wc_b[n];
            g_alpha[rr * F_ + n] = 1.f / (1.f + expf(-s));
        }
    }
}

// ---------------- distributed-flag grid barrier ----------------
__device__ __forceinline__ void gbar(unsigned target) {
    __syncthreads();
    if (threadIdx.x == 0) {
        __threadfence();
        atomicExch(&g_flags[blockIdx.x * 8], target);
    }
    if (threadIdx.x < GRID_MAIN) {
        const volatile unsigned* fl = (const volatile unsigned*)&g_flags[threadIdx.x * 8];
        while (*fl < target) { __nanosleep(32); }
    }
    __syncthreads();
    __threadfence();
}

// smem byte offsets
#define SM_RED 0
#define SM_XS  64                   // chain xc staging 2*128*4 = 1024 B
#define SM_BUF 2048                 // 2 buffers x 32KB: Ahi,Alo,Bhi,Blo x 8KB
#define SMEM_BYTES (SM_BUF + 2 * 32768)

// 64x64x64 bf16 split-MMA chunk: acc[nb][4] += A(hi/lo) x B(hi/lo)
__device__ __forceinline__ void mma_chunk(unsigned base, bool has_lo,
                                          float acc[4][4], int lane, int wr, int wcl) {
    const unsigned ahi = base, alo = base + 8192u, bhi = base + 16384u, blo = base + 24576u;
    const int arow = wr * 16 + (lane & 15);
    const int aswz = (arow & 7);
    #pragma unroll
    for (int ks = 0; ks < 4; ks++) {
        const int achk = ks * 2 + (lane >> 4);
        const unsigned aoff = (unsigned)(arow * 128 + ((achk ^ aswz) << 4));
        uint32_t Ahi[4], Alo[4];
        ldsm_x4(Ahi, ahi + aoff);
        if (has_lo) ldsm_x4(Alo, alo + aoff);
        #pragma unroll
        for (int nb = 0; nb < 4; nb++) {
            const int brow = wcl * 32 + nb * 8 + (lane & 7);
            const int bchk = ks * 2 + ((lane >> 3) & 1);
            const unsigned boff = (unsigned)(brow * 128 + ((bchk ^ (brow & 7)) << 4));
            uint32_t Bhi[2], Blo[2];
            ldsm_x2(Bhi, bhi + boff);
            ldsm_x2(Blo, blo + boff);
            mma16816(acc[nb], Ahi, Bhi);
            if (has_lo) mma16816(acc[nb], Alo, Bhi);
            mma16816(acc[nb], Ahi, Blo);
        }
    }
}

// ---------------- the persistent main kernel ----------------
__global__ __launch_bounds__(THREADS_MAIN, 1) void k_main(
    const float* __restrict__ x_all, const float* __restrict__ m_all,
    const float* __restrict__ tx_all, const float* __restrict__ ev_all,
    const float* __restrict__ hist_b, const float* __restrict__ feat_b,
    float* __restrict__ out) {
    extern __shared__ char smem[];
    const unsigned sm = (unsigned)__cvta_generic_to_shared(smem);
    float* red = (float*)(smem + SM_RED);
    float* xs  = (float*)(smem + SM_XS);
    float* Gs  = (float*)(smem + SM_BUF);   // alias buffer0 for gate epilogue

    const int tid = threadIdx.x;
    const int lane = tid & 31;
    const int wid = tid >> 5;
    const int wr = wid & 3, wcl = wid >> 2;      // warp 16x32 tile in 64x64
    const int bi = blockIdx.x;
    const int rg = bi / 34, ct = bi % 34;        // row-group, col-tile
    const int row0 = rg * 64;
    const bool is_hist = (ct >= 32);
    const int nb0 = is_hist ? (2048 + (ct - 32) * 64) : (ct * 64);
    const unsigned buf[2] = { sm + SM_BUF, sm + SM_BUF + 32768u };

    float cstate[4] = {0.f, 0.f, 0.f, 0.f};
    unsigned bar = 0;

    for (int t = 0; t < T_; t++) {
        float acc[4][4] = {};

        // ============ P1: K 256..768, A = hdec (hi/lo) ============
        {
            // stage chunk 0
            for (int i = tid; i < 2048; i += THREADS_MAIN) {
                int mat = i >> 9, g = i & 511, r = g >> 3, p = g & 7;
                unsigned dst = buf[0] + (unsigned)(mat * 8192 + r * 128 + ((p ^ (r & 7)) << 4));
                const void* src;
                if (mat == 0)      src = g_hd16hi + (row0 + r) * H_ + p * 8;
                else if (mat == 1) src = g_hd16lo + (row0 + r) * H_ + p * 8;
                else if (mat == 2) src = g_Bhi + (size_t)(nb0 + r) * 768 + 256 + p * 8;
                else               src = g_Blo + (size_t)(nb0 + r) * 768 + 256 + p * 8;
                cpa16(dst, src);
            }
            cp_commit();
            for (int c = 0; c < 8; c++) {
                if (c + 1 < 8) {
                    int k0 = (c + 1) * 64;
                    unsigned bb = buf[(c + 1) & 1];
                    for (int i = tid; i < 2048; i += THREADS_MAIN) {
                        int mat = i >> 9, g = i & 511, r = g >> 3, p = g & 7;
                        unsigned dst = bb + (unsigned)(mat * 8192 + r * 128 + ((p ^ (r & 7)) << 4));
                        const void* src;
                        if (mat == 0)      src = g_hd16hi + (row0 + r) * H_ + k0 + p * 8;
                        else if (mat == 1) src = g_hd16lo + (row0 + r) * H_ + k0 + p * 8;
                        else if (mat == 2) src = g_Bhi + (size_t)(nb0 + r) * 768 + 256 + k0 + p * 8;
                        else               src = g_Blo + (size_t)(nb0 + r) * 768 + 256 + k0 + p * 8;
                        cpa16(dst, src);
                    }
                    cp_commit();
                    cp_wait1();
                } else {
                    cp_wait0();
                }
                __syncthreads();
                mma_chunk(buf[c & 1], true, acc, lane, wr, wcl);
                __syncthreads();
            }
        }
        // hist CTAs: write x_hist (+hist_b) from register acc
        if (is_hist) {
            const int r0 = wr * 16 + (lane >> 2);
            const int c0g = wcl * 32 + (lane & 3) * 2;
            #pragma unroll
            for (int nb = 0; nb < 4; nb++) {
                #pragma unroll
                for (int q = 0; q < 4; q++) {
                    int r = r0 + ((q >> 1) << 3);
                    int fc = (ct - 32) * 64 + c0g + nb * 8 + (q & 1);
                    __stcg(&g_xhist[(row0 + r) * F_ + fc], acc[nb][q] + hist_b[fc]);
                }
            }
        }
        gbar(++bar);

        // ============ chain: rows 2bi, 2bi+1 (CTAs 0..127) ============
        if (bi < 128) {
            const int rr = tid >> 7, f = tid & 127;
            const int prow = bi * 2 + rr;
            float xh = __ldcg(&g_xhist[prow * F_ + f]);
            int base = (prow * T_ + t) * F_ + f;
            float mv = m_all[base], xv = x_all[base];
            xs[rr * 128 + f] = mv * xv + (1.f - mv) * xh;
            __syncthreads();
            float z = feat_b[f];
            const float* xrow = xs + rr * 128;
            #pragma unroll 8
            for (int k = 0; k < 128; k++) z += xrow[k] * g_featT[k * F_ + f];
            float al = g_alpha[((size_t)t * B_ + prow) * F_ + f];
            float ch = al * z + (1.f - al) * xh;
            float cc = mv * xv + (1.f - mv) * ch;
            out[base] = cc;
            __nv_bfloat16 hi = __float2bfloat16(cc);
            __stcg(&g_cc16hi[prow * F_ + f], hi);
            __stcg(&g_cc16lo[prow * F_ + f], __float2bfloat16(cc - __bfloat162float(hi)));
            float tg = tx_all[base], evv = ev_all[base];
            float e1 = xh - tg, e2 = z - tg, e3 = ch - tg;
            float l = evv * (e1 * e1 + e2 * e2 + e3 * e3);
            #pragma unroll
            for (int off = 16; off > 0; off >>= 1) l += __shfl_down_sync(0xffffffffu, l, off);
            int ln = tid & 31, w = tid >> 5;
            if (ln == 0) red[w] = l;
            __syncthreads();
            if (tid == 0) {
                float tot = 0.f;
                #pragma unroll
                for (int i = 0; i < 8; i++) tot += red[i];
                atomicAdd(&g_loss, (double)tot / ((double)g_denom[t] * (double)T_));
            }
        }
        gbar(++bar);
        if (t == T_ - 1) break;

        // ============ P2: K 0..256, A = [cc | m], then LSTM ============
        if (!is_hist) {
            // stage chunk 0 (cc hi/lo)
            for (int i = tid; i < 2048; i += THREADS_MAIN) {
                int mat = i >> 9, g = i & 511, r = g >> 3, p = g & 7;
                unsigned dst = buf[0] + (unsigned)(mat * 8192 + r * 128 + ((p ^ (r & 7)) << 4));
                const void* src;
                if (mat == 0)      src = g_cc16hi + (row0 + r) * F_ + p * 8;
                else if (mat == 1) src = g_cc16lo + (row0 + r) * F_ + p * 8;
                else if (mat == 2) src = g_Bhi + (size_t)(nb0 + r) * 768 + p * 8;
                else               src = g_Blo + (size_t)(nb0 + r) * 768 + p * 8;
                cpa16(dst, src);
            }
            cp_commit();
            for (int c = 0; c < 4; c++) {
                if (c + 1 < 4) {
                    int cn = c + 1;
                    unsigned bb = buf[cn & 1];
                    for (int i = tid; i < 2048; i += THREADS_MAIN) {
                        int mat = i >> 9, g = i & 511, r = g >> 3, p = g & 7;
                        if (mat == 1 && cn >= 2) continue;   // m has no lo-term
                        unsigned dst = bb + (unsigned)(mat * 8192 + r * 128 + ((p ^ (r & 7)) << 4));
                        const void* src;
                        if (mat == 0)
                            src = (cn < 2) ? (const void*)(g_cc16hi + (row0 + r) * F_ + cn * 64 + p * 8)
                                           : (const void*)(g_m16 + ((size_t)(row0 + r) * T_ + t) * F_ + (cn - 2) * 64 + p * 8);
                        else if (mat == 1)
                            src = g_cc16lo + (row0 + r) * F_ + cn * 64 + p * 8;
                        else if (mat == 2)
                            src = g_Bhi + (size_t)(nb0 + r) * 768 + cn * 64 + p * 8;
                        else
                            src = g_Blo + (size_t)(nb0 + r) * 768 + cn * 64 + p * 8;
                        cpa16(dst, src);
                    }
                    cp_commit();
                    cp_wait1();
                } else {
                    cp_wait0();
                }
                __syncthreads();
                mma_chunk(buf[c & 1], c < 2, acc, lane, wr, wcl);
                __syncthreads();
            }
            // epilogue: Gs = acc + bias (Gs aliases buffer0 — all MMA reads done)
            {
                const int r0 = wr * 16 + (lane >> 2);
                const int c0g = wcl * 32 + (lane & 3) * 2;
                #pragma unroll
                for (int nb = 0; nb < 4; nb++) {
                    #pragma unroll
                    for (int q = 0; q < 4; q++) {
                        int r = r0 + ((q >> 1) << 3);
                        int c = c0g + nb * 8 + (q & 1);
                        Gs[r * 64 + c] = acc[nb][q] + g_biasp[ct * 64 + c];
                    }
                }
            }
            __syncthreads();
            // LSTM on block-exclusive cells (64 rows x 16 j's), c-state in regs
            #pragma unroll
            for (int u = 0; u < 4; u++) {
                int cell = u * 256 + tid;
                int r = cell >> 4, jj = cell & 15;
                float ig = Gs[r * 64 + jj];
                float fg = Gs[r * 64 + 16 + jj];
                float gg = Gs[r * 64 + 32 + jj];
                float og = Gs[r * 64 + 48 + jj];
                float cn = sigf(fg) * cstate[u] + sigf(ig) * tanhf(gg);
                cstate[u] = cn;
                float h = sigf(og) * tanhf(cn);
                int gidx = (row0 + r) * H_ + ct * 16 + jj;
                float hd = h * g_gammah[(size_t)(t + 1) * B_ * H_ + gidx];
                __nv_bfloat16 hi = __float2bfloat16(hd);
                __stcg(&g_hd16hi[gidx], hi);
                __stcg(&g_hd16lo[gidx], __float2bfloat16(hd - __bfloat162float(hi)));
            }
        }
        gbar(++bar);
    }
}

// ---------------- finalize ----------------
__global__ void k_finish(float* __restrict__ out, int out_size) {
    out[out_size - 1] = (float)g_loss;
}

// ---------------- launch ----------------
extern "C" void kernel_launch(void* const* d_in, const int* in_sizes, int n_in,
                              void* d_out, int out_size) {
    const float* x      = (const float*)d_in[0];
    const float* m      = (const float*)d_in[1];
    const float* d      = (const float*)d_in[2];
    const float* tx     = (const float*)d_in[3];
    const float* ev     = (const float*)d_in[4];
    const float* td_h_W = (const float*)d_in[5];
    const float* td_h_b = (const float*)d_in[6];
    const float* td_x_W = (const float*)d_in[7];
    const float* td_x_b = (const float*)d_in[8];
    const float* hist_W = (const float*)d_in[9];
    const float* hist_b = (const float*)d_in[10];
    const float* feat_W = (const float*)d_in[11];
    const float* feat_b = (const float*)d_in[12];
    const float* wc_W   = (const float*)d_in[13];
    const float* wc_b   = (const float*)d_in[14];
    const float* W_ih   = (const float*)d_in[15];
    const float* W_hh   = (const float*)d_in[16];
    const float* b_ih   = (const float*)d_in[17];
    const float* b_hh   = (const float*)d_in[18];
    float* out = (float*)d_out;

    static int smem_set = 0;
    if (!smem_set) {
        cudaFuncSetAttribute(k_main, cudaFuncAttributeMaxDynamicSharedMemorySize, SMEM_BYTES);
        smem_set = 1;
    }

    k_init<<<512, 256>>>(feat_W);
    k_prep<<<1024, 256>>>(W_ih, W_hh, hist_W, b_ih, b_hh, m);
    k_denom<<<T_, 256>>>(ev);
    k_gammah<<<dim3(H_ / PBN, (T_ * B_) / PBM), 256>>>(d, td_h_W, td_h_b);
    k_alpha<<<dim3(F_ / PBN, (T_ * B_) / PBM), 256>>>(d, m, td_x_W, td_x_b, wc_W, wc_b);
    k_main<<<GRID_MAIN, THREADS_MAIN, SMEM_BYTES>>>(x, m, tx, ev, hist_b, feat_b, out);
    k_finish<<<1, 1>>>(out, out_size);
}

// round 6
// speedup vs baseline: 4.8839x; 1.1294x over previous
#include <cuda_runtime.h>
#include <cuda_bf16.h>
#include <math.h>
#include <stdint.h>

// Problem dims
#define B_  256
#define T_  128
#define F_  128
#define H_  512
#define NCOMB 2176          // 2048 permuted gate cols + 128 hist cols
#define GRID_MAIN 136       // 4 row-groups x 34 col-tiles
#define THREADS_MAIN 256

// ---------------- persistent device state / scratch ----------------
__device__ float          g_gammah[T_ * B_ * H_];   // [t][b][j]
__device__ float          g_alpha [T_ * B_ * F_];   // [t][b][f]
__device__ __nv_bfloat16  g_hd16hi[B_ * H_];
__device__ __nv_bfloat16  g_hd16lo[B_ * H_];
__device__ __nv_bfloat16  g_cc16hi[B_ * F_];
__device__ __nv_bfloat16  g_cc16lo[B_ * F_];
__device__ __nv_bfloat16  g_m16   [B_ * T_ * F_];
__device__ __nv_bfloat16  g_Bhi   [NCOMB * 768];    // [n'][k], gate cols permuted
__device__ __nv_bfloat16  g_Blo   [NCOMB * 768];
__device__ float          g_biasp [2048];           // permuted b_ih + b_hh
__device__ float          g_xhist [B_ * F_];        // includes hist_b
__device__ float          g_featT [F_ * F_];        // featT[k][f], diag zeroed
__device__ float          g_denom [T_];
__device__ double         g_loss;
__device__ unsigned       g_flags [GRID_MAIN * 8];

__device__ __forceinline__ float sigf(float v) { return 1.f / (1.f + expf(-v)); }

// ---------------- mma / ldmatrix helpers (base-arch, NOT tcgen05) ----------------
__device__ __forceinline__ void ldsm_x4(uint32_t* r, unsigned addr) {
    asm volatile("ldmatrix.sync.aligned.m8n8.x4.shared.b16 {%0,%1,%2,%3}, [%4];"
                 : "=r"(r[0]), "=r"(r[1]), "=r"(r[2]), "=r"(r[3]) : "r"(addr));
}
__device__ __forceinline__ void mma16816(float* d, const uint32_t* a, const uint32_t* b) {
    asm volatile("mma.sync.aligned.m16n8k16.row.col.f32.bf16.bf16.f32 "
                 "{%0,%1,%2,%3}, {%4,%5,%6,%7}, {%8,%9}, {%0,%1,%2,%3};"
                 : "+f"(d[0]), "+f"(d[1]), "+f"(d[2]), "+f"(d[3])
                 : "r"(a[0]), "r"(a[1]), "r"(a[2]), "r"(a[3]), "r"(b[0]), "r"(b[1]));
}
__device__ __forceinline__ void cpa16(unsigned dst, const void* src) {
    asm volatile("cp.async.cg.shared.global [%0], [%1], 16;" :: "r"(dst), "l"(src) : "memory");
}
__device__ __forceinline__ void cp_commit() { asm volatile("cp.async.commit_group;" ::: "memory"); }
__device__ __forceinline__ void cp_wait0()  { asm volatile("cp.async.wait_group 0;" ::: "memory"); }

// ---------------- init ----------------
__global__ void k_init(const float* __restrict__ feat_W) {
    int idx = blockIdx.x * blockDim.x + threadIdx.x;   // 131072 threads
    if (idx < B_ * H_) {
        g_hd16hi[idx] = __float2bfloat16(0.f);
        g_hd16lo[idx] = __float2bfloat16(0.f);
    }
    if (idx == 0) g_loss = 0.0;
    if (idx < GRID_MAIN * 8) g_flags[idx] = 0u;
    if (idx < F_ * F_) {
        int k = idx >> 7, f = idx & 127;
        g_featT[idx] = (f == k) ? 0.f : feat_W[f * F_ + k];
    }
}

// ---------------- weight split (permuted) + m bf16 + bias ----------------
__global__ void k_prep(const float* __restrict__ W_ih, const float* __restrict__ W_hh,
                       const float* __restrict__ hist_W,
                       const float* __restrict__ b_ih, const float* __restrict__ b_hh,
                       const float* __restrict__ m_all) {
    int stride = gridDim.x * blockDim.x;
    int tid0 = blockIdx.x * blockDim.x + threadIdx.x;
    for (int idx = tid0; idx < NCOMB * 768; idx += stride) {
        int np = idx / 768, k = idx - np * 768;
        float w;
        if (np < 2048) {
            int ct = np >> 6, c = np & 63;
            int n = (c >> 4) * 512 + (ct << 4) + (c & 15);   // gate-interleaved permute
            w = (k < 256) ? W_ih[n * 256 + k] : W_hh[n * 512 + (k - 256)];
        } else {
            int f = np - 2048;
            w = (k < 256) ? 0.f : hist_W[f * 512 + (k - 256)];
        }
        __nv_bfloat16 hi = __float2bfloat16(w);
        g_Bhi[idx] = hi;
        g_Blo[idx] = __float2bfloat16(w - __bfloat162float(hi));
    }
    for (int idx = tid0; idx < B_ * T_ * F_; idx += stride)
        g_m16[idx] = __float2bfloat16(m_all[idx]);
    for (int idx = tid0; idx < 2048; idx += stride) {
        int ct = idx >> 6, c = idx & 63;
        int n = (c >> 4) * 512 + (ct << 4) + (c & 15);
        g_biasp[idx] = b_ih[n] + b_hh[n];
    }
}

// ---------------- denom[t] ----------------
__global__ void k_denom(const float* __restrict__ ev_all) {
    int t = blockIdx.x;
    float s = 0.f;
    for (int i = threadIdx.x; i < B_ * F_; i += 256) {
        int b = i >> 7, f = i & 127;
        s += ev_all[(b * T_ + t) * F_ + f];
    }
    #pragma unroll
    for (int off = 16; off > 0; off >>= 1) s += __shfl_down_sync(0xffffffffu, s, off);
    __shared__ float rs[8];
    int lane = threadIdx.x & 31, w = threadIdx.x >> 5;
    if (lane == 0) rs[w] = s;
    __syncthreads();
    if (threadIdx.x == 0) {
        float tot = 0.f;
        #pragma unroll
        for (int i = 0; i < 8; i++) tot += rs[i];
        g_denom[t] = tot + 1e-8f;
    }
}

// ---------------- precompute GEMMs (fp32 SIMT, parallel over T) ----------------
#define PBM 64
#define PBN 64
#define PBK 32
__global__ __launch_bounds__(256) void k_gammah(const float* __restrict__ d_all,
                                                const float* __restrict__ W,
                                                const float* __restrict__ bias) {
    __shared__ float sA[PBM][PBK + 1];
    __shared__ float sB[PBK][PBN + 1];
    const int rr0 = blockIdx.y * PBM;
    const int bn  = blockIdx.x * PBN;
    const int tid = threadIdx.x;
    const int tr = tid >> 4, tc = tid & 15;
    float acc[4][4] = {};
    for (int k0 = 0; k0 < F_; k0 += PBK) {
        #pragma unroll
        for (int i = tid; i < PBM * PBK; i += 256) {
            int r = i >> 5, kk = i & 31;
            int rr = rr0 + r;
            int b = rr & 255, tt = rr >> 8;
            sA[r][kk] = d_all[(b * T_ + tt) * F_ + k0 + kk];
        }
        #pragma unroll
        for (int i = tid; i < PBK * PBN; i += 256) {
            int nl = i >> 5, kk = i & 31;
            sB[kk][nl] = W[(bn + nl) * F_ + k0 + kk];
        }
        __syncthreads();
        #pragma unroll
        for (int kk = 0; kk < PBK; kk++) {
            float a[4], bb[4];
            #pragma unroll
            for (int i = 0; i < 4; i++) a[i] = sA[tr * 4 + i][kk];
            #pragma unroll
            for (int j = 0; j < 4; j++) bb[j] = sB[kk][tc * 4 + j];
            #pragma unroll
            for (int i = 0; i < 4; i++)
                #pragma unroll
                for (int j = 0; j < 4; j++) acc[i][j] += a[i] * bb[j];
        }
        __syncthreads();
    }
    #pragma unroll
    for (int i = 0; i < 4; i++) {
        int rr = rr0 + tr * 4 + i;
        #pragma unroll
        for (int j = 0; j < 4; j++) {
            int n = bn + tc * 4 + j;
            float v = acc[i][j] + bias[n];
            g_gammah[(size_t)rr * H_ + n] = expf(-fmaxf(v, 0.f));
        }
    }
}

__global__ __launch_bounds__(256) void k_alpha(const float* __restrict__ d_all,
                                               const float* __restrict__ m_all,
                                               const float* __restrict__ tdx_W,
                                               const float* __restrict__ tdx_b,
                                               const float* __restrict__ wc_W,
                                               const float* __restrict__ wc_b) {
    __shared__ float sA[PBM][PBK + 1];
    __shared__ float sB[PBK][PBN + 1];
    const int rr0 = blockIdx.y * PBM;
    const int bn  = blockIdx.x * PBN;
    const int tid = threadIdx.x;
    const int tr = tid >> 4, tc = tid & 15;
    float acc[4][4] = {};
    for (int k0 = 0; k0 < 2 * F_; k0 += PBK) {
        #pragma unroll
        for (int i = tid; i < PBM * PBK; i += 256) {
            int r = i >> 5, kk = i & 31;
            int rr = rr0 + r;
            int b = rr & 255, tt = rr >> 8;
            int k = k0 + kk;
            float v;
            if (k < F_) {
                float dv = d_all[(b * T_ + tt) * F_ + k];
                float gv = dv * tdx_W[k * F_ + k] + tdx_b[k];
                v = expf(-fmaxf(gv, 0.f));
            } else {
                v = m_all[(b * T_ + tt) * F_ + (k - F_)];
            }
            sA[r][kk] = v;
        }
        #pragma unroll
        for (int i = tid; i < PBK * PBN; i += 256) {
            int nl = i >> 5, kk = i & 31;
            sB[kk][nl] = wc_W[(bn + nl) * 2 * F_ + k0 + kk];
        }
        __syncthreads();
        #pragma unroll
        for (int kk = 0; kk < PBK; kk++) {
            float a[4], bb[4];
            #pragma unroll
            for (int i = 0; i < 4; i++) a[i] = sA[tr * 4 + i][kk];
            #pragma unroll
            for (int j = 0; j < 4; j++) bb[j] = sB[kk][tc * 4 + j];
            #pragma unroll
            for (int i = 0; i < 4; i++)
                #pragma unroll
                for (int j = 0; j < 4; j++) acc[i][j] += a[i] * bb[j];
        }
        __syncthreads();
    }
    #pragma unroll
    for (int i = 0; i < 4; i++) {
        int rr = rr0 + tr * 4 + i;
        #pragma unroll
        for (int j = 0; j < 4; j++) {
            int n = bn + tc * 4 + j;
            float s = acc[i][j] + wc_b[n];
            g_alpha[rr * F_ + n] = 1.f / (1.f + expf(-s));
        }
    }
}

// ---------------- distributed-flag grid barrier ----------------
__device__ __forceinline__ void gbar(unsigned target) {
    __syncthreads();
    if (threadIdx.x == 0) {
        __threadfence();
        atomicExch(&g_flags[blockIdx.x * 8], target);
    }
    if (threadIdx.x < GRID_MAIN) {
        const volatile unsigned* fl = (const volatile unsigned*)&g_flags[threadIdx.x * 8];
        while (*fl < target) { __nanosleep(32); }
    }
    __syncthreads();
    __threadfence();
}

// smem byte offsets
#define SM_RED 0                     // 128 B
#define SM_XS  128                   // 2*128 floats = 1024 B
#define SM_A   2048                  // 2 buffers x 16KB (Ahi 8KB + Alo 8KB)
#define SM_W   (SM_A + 32768)        // weights: WHI 96KB (12 chunks x 8KB) + WLO 96KB
#define SMEM_BYTES (SM_W + 196608)   // 231424 <= 232448

// 64x64x64 bf16 split-MMA chunk: A from staged buffer, B from resident weights
__device__ __forceinline__ void mma_chunk(unsigned abase, unsigned whi, unsigned wlo,
                                          bool has_alo, float acc[4][4],
                                          int lane, int wr, int wcl) {
    const unsigned ahi = abase, alo = abase + 8192u;
    const int arow = wr * 16 + (lane & 15);
    const int aswz = arow & 7;
    #pragma unroll
    for (int ks = 0; ks < 4; ks++) {
        const int achk = ks * 2 + (lane >> 4);
        const unsigned aoff = (unsigned)(arow * 128 + ((achk ^ aswz) << 4));
        uint32_t Ahi[4], Alo[4];
        ldsm_x4(Ahi, ahi + aoff);
        if (has_alo) ldsm_x4(Alo, alo + aoff);
        uint32_t Bhi[8], Blo[8];
        #pragma unroll
        for (int pair = 0; pair < 2; pair++) {
            const int brow = wcl * 32 + pair * 16 + ((lane >> 4) << 3) + (lane & 7);
            const int bchk = ks * 2 + ((lane >> 3) & 1);
            const unsigned boff = (unsigned)(brow * 128 + ((bchk ^ (brow & 7)) << 4));
            ldsm_x4(Bhi + pair * 4, whi + boff);
            ldsm_x4(Blo + pair * 4, wlo + boff);
        }
        #pragma unroll
        for (int nb = 0; nb < 4; nb++) {
            mma16816(acc[nb], Ahi, Bhi + nb * 2);
            if (has_alo) mma16816(acc[nb], Alo, Bhi + nb * 2);
            mma16816(acc[nb], Ahi, Blo + nb * 2);
        }
    }
}

// ---------------- the persistent main kernel ----------------
__global__ __launch_bounds__(THREADS_MAIN, 1) void k_main(
    const float* __restrict__ x_all, const float* __restrict__ m_all,
    const float* __restrict__ tx_all, const float* __restrict__ ev_all,
    const float* __restrict__ hist_b, const float* __restrict__ feat_b,
    float* __restrict__ out) {
    extern __shared__ char smem[];
    const unsigned sm = (unsigned)__cvta_generic_to_shared(smem);
    float* red = (float*)(smem + SM_RED);
    float* xs  = (float*)(smem + SM_XS);
    float* Gs  = (float*)(smem + SM_A);   // aliases A buffer0 for gate epilogue

    const int tid = threadIdx.x;
    const int lane = tid & 31;
    const int wid = tid >> 5;
    const int wr = wid & 3, wcl = wid >> 2;      // warp 16x32 tile in 64x64
    const int bi = blockIdx.x;
    const int rg = bi / 34, ct = bi % 34;        // row-group, col-tile
    const int row0 = rg * 64;
    const bool is_hist = (ct >= 32);
    const int nb0 = is_hist ? (2048 + (ct - 32) * 64) : (ct * 64);
    const unsigned buf[2] = { sm + SM_A, sm + SM_A + 16384u };
    const unsigned WHI = sm + SM_W, WLO = sm + SM_W + 98304u;

    // ---- one-time: resident weight load (12 chunks hi + lo) ----
    for (int i = tid; i < 12288; i += THREADS_MAIN) {
        int mat = i / 6144, rem = i - mat * 6144;
        int c = rem >> 9, g = rem & 511, r = g >> 3, p = g & 7;
        unsigned dst = (mat ? WLO : WHI) + (unsigned)(c * 8192 + r * 128 + ((p ^ (r & 7)) << 4));
        const __nv_bfloat16* src = (mat ? g_Blo : g_Bhi) + (size_t)(nb0 + r) * 768 + c * 64 + p * 8;
        cpa16(dst, src);
    }
    cp_commit();
    cp_wait0();
    __syncthreads();

    float cstate[4] = {0.f, 0.f, 0.f, 0.f};
    unsigned bar = 0;

    for (int t = 0; t < T_; t++) {
        float acc[4][4] = {};

        // ============ P1: K 256..768, A = hdec (hi/lo), weight chunks 4..11 ============
        {
            // stage chunk 0
            for (int i = tid; i < 1024; i += THREADS_MAIN) {
                int mat = i >> 9, g = i & 511, r = g >> 3, p = g & 7;
                unsigned dst = buf[0] + (unsigned)(mat * 8192 + r * 128 + ((p ^ (r & 7)) << 4));
                const __nv_bfloat16* src = (mat ? g_hd16lo : g_hd16hi) + (row0 + r) * H_ + p * 8;
                cpa16(dst, src);
            }
            cp_commit();
            for (int c = 0; c < 8; c++) {
                cp_wait0();
                __syncthreads();
                if (c < 7) {
                    int k0 = (c + 1) * 64;
                    unsigned bb = buf[(c + 1) & 1];
                    for (int i = tid; i < 1024; i += THREADS_MAIN) {
                        int mat = i >> 9, g = i & 511, r = g >> 3, p = g & 7;
                        unsigned dst = bb + (unsigned)(mat * 8192 + r * 128 + ((p ^ (r & 7)) << 4));
                        const __nv_bfloat16* src = (mat ? g_hd16lo : g_hd16hi) + (row0 + r) * H_ + k0 + p * 8;
                        cpa16(dst, src);
                    }
                    cp_commit();
                }
                mma_chunk(buf[c & 1], WHI + (4 + c) * 8192u, WLO + (4 + c) * 8192u,
                          true, acc, lane, wr, wcl);
            }
        }
        // hist CTAs: write x_hist (+hist_b) from register acc
        if (is_hist) {
            const int r0 = wr * 16 + (lane >> 2);
            const int c0g = wcl * 32 + (lane & 3) * 2;
            #pragma unroll
            for (int nb = 0; nb < 4; nb++) {
                #pragma unroll
                for (int q = 0; q < 4; q++) {
                    int r = r0 + ((q >> 1) << 3);
                    int fc = (ct - 32) * 64 + c0g + nb * 8 + (q & 1);
                    __stcg(&g_xhist[(row0 + r) * F_ + fc], acc[nb][q] + hist_b[fc]);
                }
            }
        }
        gbar(++bar);

        // ============ chain: rows 2bi, 2bi+1 (CTAs 0..127) ============
        if (bi < 128) {
            const int rr = tid >> 7, f = tid & 127;
            const int prow = bi * 2 + rr;
            float xh = __ldcg(&g_xhist[prow * F_ + f]);
            int base = (prow * T_ + t) * F_ + f;
            float mv = m_all[base], xv = x_all[base];
            xs[rr * 128 + f] = mv * xv + (1.f - mv) * xh;
            __syncthreads();
            float z = feat_b[f];
            const float* xrow = xs + rr * 128;
            #pragma unroll 8
            for (int k = 0; k < 128; k++) z += xrow[k] * g_featT[k * F_ + f];
            float al = g_alpha[((size_t)t * B_ + prow) * F_ + f];
            float ch = al * z + (1.f - al) * xh;
            float cc = mv * xv + (1.f - mv) * ch;
            out[base] = cc;
            __nv_bfloat16 hi = __float2bfloat16(cc);
            __stcg(&g_cc16hi[prow * F_ + f], hi);
            __stcg(&g_cc16lo[prow * F_ + f], __float2bfloat16(cc - __bfloat162float(hi)));
            float tg = tx_all[base], evv = ev_all[base];
            float e1 = xh - tg, e2 = z - tg, e3 = ch - tg;
            float l = evv * (e1 * e1 + e2 * e2 + e3 * e3);
            #pragma unroll
            for (int off = 16; off > 0; off >>= 1) l += __shfl_down_sync(0xffffffffu, l, off);
            int ln = tid & 31, w = tid >> 5;
            if (ln == 0) red[w] = l;
            __syncthreads();
            if (tid == 0) {
                float tot = 0.f;
                #pragma unroll
                for (int i = 0; i < 8; i++) tot += red[i];
                atomicAdd(&g_loss, (double)tot / ((double)g_denom[t] * (double)T_));
            }
        }
        gbar(++bar);
        if (t == T_ - 1) break;

        // ============ P2: K 0..256, A = [cc | m], weight chunks 0..3, then LSTM ============
        if (!is_hist) {
            // stage chunk 0 (cc hi/lo)
            for (int i = tid; i < 1024; i += THREADS_MAIN) {
                int mat = i >> 9, g = i & 511, r = g >> 3, p = g & 7;
                unsigned dst = buf[0] + (unsigned)(mat * 8192 + r * 128 + ((p ^ (r & 7)) << 4));
                const __nv_bfloat16* src = (mat ? g_cc16lo : g_cc16hi) + (row0 + r) * F_ + p * 8;
                cpa16(dst, src);
            }
            cp_commit();
            for (int c = 0; c < 4; c++) {
                cp_wait0();
                __syncthreads();
                if (c < 3) {
                    int cn = c + 1;
                    unsigned bb = buf[cn & 1];
                    int lim = (cn < 2) ? 1024 : 512;   // m has no lo-term
                    for (int i = tid; i < lim; i += THREADS_MAIN) {
                        int mat = i >> 9, g = i & 511, r = g >> 3, p = g & 7;
                        unsigned dst = bb + (unsigned)(mat * 8192 + r * 128 + ((p ^ (r & 7)) << 4));
                        const __nv_bfloat16* src;
                        if (mat == 0)
                            src = (cn < 2) ? g_cc16hi + (row0 + r) * F_ + cn * 64 + p * 8
                                           : g_m16 + ((size_t)(row0 + r) * T_ + t) * F_ + (cn - 2) * 64 + p * 8;
                        else
                            src = g_cc16lo + (row0 + r) * F_ + cn * 64 + p * 8;
                        cpa16(dst, src);
                    }
                    cp_commit();
                }
                mma_chunk(buf[c & 1], WHI + c * 8192u, WLO + c * 8192u,
                          c < 2, acc, lane, wr, wcl);
            }
            // epilogue: Gs = acc + bias (Gs aliases buf0; mma(3) reads buf1 only)
            {
                const int r0 = wr * 16 + (lane >> 2);
                const int c0g = wcl * 32 + (lane & 3) * 2;
                #pragma unroll
                for (int nb = 0; nb < 4; nb++) {
                    #pragma unroll
                    for (int q = 0; q < 4; q++) {
                        int r = r0 + ((q >> 1) << 3);
                        int c = c0g + nb * 8 + (q & 1);
                        Gs[r * 64 + c] = acc[nb][q] + g_biasp[ct * 64 + c];
                    }
                }
            }
            __syncthreads();
            // LSTM on block-exclusive cells (64 rows x 16 j's), c-state in regs
            #pragma unroll
            for (int u = 0; u < 4; u++) {
                int cell = u * 256 + tid;
                int r = cell >> 4, jj = cell & 15;
                float ig = Gs[r * 64 + jj];
                float fg = Gs[r * 64 + 16 + jj];
                float gg = Gs[r * 64 + 32 + jj];
                float og = Gs[r * 64 + 48 + jj];
                float cn = sigf(fg) * cstate[u] + sigf(ig) * tanhf(gg);
                cstate[u] = cn;
                float h = sigf(og) * tanhf(cn);
                int gidx = (row0 + r) * H_ + ct * 16 + jj;
                float hd = h * g_gammah[(size_t)(t + 1) * B_ * H_ + gidx];
                __nv_bfloat16 hi = __float2bfloat16(hd);
                __stcg(&g_hd16hi[gidx], hi);
                __stcg(&g_hd16lo[gidx], __float2bfloat16(hd - __bfloat162float(hi)));
            }
        }
        gbar(++bar);
    }
}

// ---------------- finalize ----------------
__global__ void k_finish(float* __restrict__ out, int out_size) {
    out[out_size - 1] = (float)g_loss;
}

// ---------------- launch ----------------
extern "C" void kernel_launch(void* const* d_in, const int* in_sizes, int n_in,
                              void* d_out, int out_size) {
    const float* x      = (const float*)d_in[0];
    const float* m      = (const float*)d_in[1];
    const float* d      = (const float*)d_in[2];
    const float* tx     = (const float*)d_in[3];
    const float* ev     = (const float*)d_in[4];
    const float* td_h_W = (const float*)d_in[5];
    const float* td_h_b = (const float*)d_in[6];
    const float* td_x_W = (const float*)d_in[7];
    const float* td_x_b = (const float*)d_in[8];
    const float* hist_W = (const float*)d_in[9];
    const float* hist_b = (const float*)d_in[10];
    const float* feat_W = (const float*)d_in[11];
    const float* feat_b = (const float*)d_in[12];
    const float* wc_W   = (const float*)d_in[13];
    const float* wc_b   = (const float*)d_in[14];
    const float* W_ih   = (const float*)d_in[15];
    const float* W_hh   = (const float*)d_in[16];
    const float* b_ih   = (const float*)d_in[17];
    const float* b_hh   = (const float*)d_in[18];
    float* out = (float*)d_out;

    static int smem_set = 0;
    if (!smem_set) {
        cudaFuncSetAttribute(k_main, cudaFuncAttributeMaxDynamicSharedMemorySize, SMEM_BYTES);
        smem_set = 1;
    }

    k_init<<<512, 256>>>(feat_W);
    k_prep<<<1024, 256>>>(W_ih, W_hh, hist_W, b_ih, b_hh, m);
    k_denom<<<T_, 256>>>(ev);
    k_gammah<<<dim3(H_ / PBN, (T_ * B_) / PBM), 256>>>(d, td_h_W, td_h_b);
    k_alpha<<<dim3(F_ / PBN, (T_ * B_) / PBM), 256>>>(d, m, td_x_W, td_x_b, wc_W, wc_b);
    k_main<<<GRID_MAIN, THREADS_MAIN, SMEM_BYTES>>>(x, m, tx, ev, hist_b, feat_b, out);
    k_finish<<<1, 1>>>(out, out_size);
}

// round 7
// speedup vs baseline: 4.9785x; 1.0194x over previous
#include <cuda_runtime.h>
#include <cuda_bf16.h>
#include <math.h>
#include <stdint.h>

// Problem dims
#define B_  256
#define T_  128
#define F_  128
#define H_  512
#define NCOMB 2176          // 2048 permuted gate cols + 128 hist cols
#define GRID_MAIN 136       // 4 row-groups x 34 col-tiles
#define THREADS_MAIN 256

// ---------------- persistent device state / scratch ----------------
__device__ float          g_gammah[T_ * B_ * H_];   // [t][b][j]
__device__ float          g_alpha [T_ * B_ * F_];   // [t][b][f]
__device__ __nv_bfloat16  g_hd16hi[B_ * H_];
__device__ __nv_bfloat16  g_hd16lo[B_ * H_];
__device__ __nv_bfloat16  g_cc16hi[B_ * F_];
__device__ __nv_bfloat16  g_cc16lo[B_ * F_];
__device__ __nv_bfloat16  g_m16   [B_ * T_ * F_];
__device__ __nv_bfloat16  g_Bhi   [NCOMB * 768];    // [n'][k], gate cols permuted
__device__ __nv_bfloat16  g_Blo   [NCOMB * 768];
__device__ float          g_biasp [2048];           // permuted b_ih + b_hh
__device__ float          g_xhist [B_ * F_];        // includes hist_b
__device__ float          g_featT [F_ * F_];        // featT[k][f], diag zeroed
__device__ float          g_denom [T_];
__device__ double         g_loss;
// per-producer flags (32B apart): G = end-of-step hdec, H = xhist, C = chain cc
__device__ unsigned       g_flagG[4 * 32 * 8];
__device__ unsigned       g_flagH[4 * 2 * 8];
__device__ unsigned       g_flagC[4 * 32 * 8];

__device__ __forceinline__ float sigf(float v) { return 1.f / (1.f + expf(-v)); }

// ---------------- mma / ldmatrix helpers (base-arch, NOT tcgen05) ----------------
__device__ __forceinline__ void ldsm_x4(uint32_t* r, unsigned addr) {
    asm volatile("ldmatrix.sync.aligned.m8n8.x4.shared.b16 {%0,%1,%2,%3}, [%4];"
                 : "=r"(r[0]), "=r"(r[1]), "=r"(r[2]), "=r"(r[3]) : "r"(addr));
}
__device__ __forceinline__ void mma16816(float* d, const uint32_t* a, const uint32_t* b) {
    asm volatile("mma.sync.aligned.m16n8k16.row.col.f32.bf16.bf16.f32 "
                 "{%0,%1,%2,%3}, {%4,%5,%6,%7}, {%8,%9}, {%0,%1,%2,%3};"
                 : "+f"(d[0]), "+f"(d[1]), "+f"(d[2]), "+f"(d[3])
                 : "r"(a[0]), "r"(a[1]), "r"(a[2]), "r"(a[3]), "r"(b[0]), "r"(b[1]));
}
__device__ __forceinline__ void cpa16(unsigned dst, const void* src) {
    asm volatile("cp.async.cg.shared.global [%0], [%1], 16;" :: "r"(dst), "l"(src) : "memory");
}
__device__ __forceinline__ void cp_commit() { asm volatile("cp.async.commit_group;" ::: "memory"); }
__device__ __forceinline__ void cp_wait0()  { asm volatile("cp.async.wait_group 0;" ::: "memory"); }
__device__ __forceinline__ void cp_wait1()  { asm volatile("cp.async.wait_group 1;" ::: "memory"); }

// ---------------- scoped flag wait / signal ----------------
__device__ __forceinline__ void waitflags(unsigned* base, int n, unsigned target) {
    if (threadIdx.x < n) {
        const volatile unsigned* fl = (const volatile unsigned*)(base + threadIdx.x * 8);
        while (*fl < target) { __nanosleep(32); }
    }
    __syncthreads();
    __threadfence();
}
__device__ __forceinline__ void signalflag(unsigned* fl, unsigned target) {
    __syncthreads();
    if (threadIdx.x == 0) {
        __threadfence();
        atomicExch(fl, target);
    }
}

// ---------------- init ----------------
__global__ void k_init(const float* __restrict__ feat_W) {
    int idx = blockIdx.x * blockDim.x + threadIdx.x;   // 131072 threads
    if (idx < B_ * H_) {
        g_hd16hi[idx] = __float2bfloat16(0.f);
        g_hd16lo[idx] = __float2bfloat16(0.f);
    }
    if (idx == 0) g_loss = 0.0;
    if (idx < 4 * 32 * 8) { g_flagG[idx] = 0u; g_flagC[idx] = 0u; }
    if (idx < 4 * 2 * 8)  g_flagH[idx] = 0u;
    if (idx < F_ * F_) {
        int k = idx >> 7, f = idx & 127;
        g_featT[idx] = (f == k) ? 0.f : feat_W[f * F_ + k];
    }
}

// ---------------- weight split (permuted) + m bf16 + bias ----------------
__global__ void k_prep(const float* __restrict__ W_ih, const float* __restrict__ W_hh,
                       const float* __restrict__ hist_W,
                       const float* __restrict__ b_ih, const float* __restrict__ b_hh,
                       const float* __restrict__ m_all) {
    int stride = gridDim.x * blockDim.x;
    int tid0 = blockIdx.x * blockDim.x + threadIdx.x;
    for (int idx = tid0; idx < NCOMB * 768; idx += stride) {
        int np = idx / 768, k = idx - np * 768;
        float w;
        if (np < 2048) {
            int ct = np >> 6, c = np & 63;
            int n = (c >> 4) * 512 + (ct << 4) + (c & 15);   // gate-interleaved permute
            w = (k < 256) ? W_ih[n * 256 + k] : W_hh[n * 512 + (k - 256)];
        } else {
            int f = np - 2048;
            w = (k < 256) ? 0.f : hist_W[f * 512 + (k - 256)];
        }
        __nv_bfloat16 hi = __float2bfloat16(w);
        g_Bhi[idx] = hi;
        g_Blo[idx] = __float2bfloat16(w - __bfloat162float(hi));
    }
    for (int idx = tid0; idx < B_ * T_ * F_; idx += stride)
        g_m16[idx] = __float2bfloat16(m_all[idx]);
    for (int idx = tid0; idx < 2048; idx += stride) {
        int ct = idx >> 6, c = idx & 63;
        int n = (c >> 4) * 512 + (ct << 4) + (c & 15);
        g_biasp[idx] = b_ih[n] + b_hh[n];
    }
}

// ---------------- denom[t] ----------------
__global__ void k_denom(const float* __restrict__ ev_all) {
    int t = blockIdx.x;
    float s = 0.f;
    for (int i = threadIdx.x; i < B_ * F_; i += 256) {
        int b = i >> 7, f = i & 127;
        s += ev_all[(b * T_ + t) * F_ + f];
    }
    #pragma unroll
    for (int off = 16; off > 0; off >>= 1) s += __shfl_down_sync(0xffffffffu, s, off);
    __shared__ float rs[8];
    int lane = threadIdx.x & 31, w = threadIdx.x >> 5;
    if (lane == 0) rs[w] = s;
    __syncthreads();
    if (threadIdx.x == 0) {
        float tot = 0.f;
        #pragma unroll
        for (int i = 0; i < 8; i++) tot += rs[i];
        g_denom[t] = tot + 1e-8f;
    }
}

// ---------------- precompute GEMMs (fp32 SIMT, parallel over T) ----------------
#define PBM 64
#define PBN 64
#define PBK 32
__global__ __launch_bounds__(256) void k_gammah(const float* __restrict__ d_all,
                                                const float* __restrict__ W,
                                                const float* __restrict__ bias) {
    __shared__ float sA[PBM][PBK + 1];
    __shared__ float sB[PBK][PBN + 1];
    const int rr0 = blockIdx.y * PBM;
    const int bn  = blockIdx.x * PBN;
    const int tid = threadIdx.x;
    const int tr = tid >> 4, tc = tid & 15;
    float acc[4][4] = {};
    for (int k0 = 0; k0 < F_; k0 += PBK) {
        #pragma unroll
        for (int i = tid; i < PBM * PBK; i += 256) {
            int r = i >> 5, kk = i & 31;
            int rr = rr0 + r;
            int b = rr & 255, tt = rr >> 8;
            sA[r][kk] = d_all[(b * T_ + tt) * F_ + k0 + kk];
        }
        #pragma unroll
        for (int i = tid; i < PBK * PBN; i += 256) {
            int nl = i >> 5, kk = i & 31;
            sB[kk][nl] = W[(bn + nl) * F_ + k0 + kk];
        }
        __syncthreads();
        #pragma unroll
        for (int kk = 0; kk < PBK; kk++) {
            float a[4], bb[4];
            #pragma unroll
            for (int i = 0; i < 4; i++) a[i] = sA[tr * 4 + i][kk];
            #pragma unroll
            for (int j = 0; j < 4; j++) bb[j] = sB[kk][tc * 4 + j];
            #pragma unroll
            for (int i = 0; i < 4; i++)
                #pragma unroll
                for (int j = 0; j < 4; j++) acc[i][j] += a[i] * bb[j];
        }
        __syncthreads();
    }
    #pragma unroll
    for (int i = 0; i < 4; i++) {
        int rr = rr0 + tr * 4 + i;
        #pragma unroll
        for (int j = 0; j < 4; j++) {
            int n = bn + tc * 4 + j;
            float v = acc[i][j] + bias[n];
            g_gammah[(size_t)rr * H_ + n] = expf(-fmaxf(v, 0.f));
        }
    }
}

__global__ __launch_bounds__(256) void k_alpha(const float* __restrict__ d_all,
                                               const float* __restrict__ m_all,
                                               const float* __restrict__ tdx_W,
                                               const float* __restrict__ tdx_b,
                                               const float* __restrict__ wc_W,
                                               const float* __restrict__ wc_b) {
    __shared__ float sA[PBM][PBK + 1];
    __shared__ float sB[PBK][PBN + 1];
    const int rr0 = blockIdx.y * PBM;
    const int bn  = blockIdx.x * PBN;
    const int tid = threadIdx.x;
    const int tr = tid >> 4, tc = tid & 15;
    float acc[4][4] = {};
    for (int k0 = 0; k0 < 2 * F_; k0 += PBK) {
        #pragma unroll
        for (int i = tid; i < PBM * PBK; i += 256) {
            int r = i >> 5, kk = i & 31;
            int rr = rr0 + r;
            int b = rr & 255, tt = rr >> 8;
            int k = k0 + kk;
            float v;
            if (k < F_) {
                float dv = d_all[(b * T_ + tt) * F_ + k];
                float gv = dv * tdx_W[k * F_ + k] + tdx_b[k];
                v = expf(-fmaxf(gv, 0.f));
            } else {
                v = m_all[(b * T_ + tt) * F_ + (k - F_)];
            }
            sA[r][kk] = v;
        }
        #pragma unroll
        for (int i = tid; i < PBK * PBN; i += 256) {
            int nl = i >> 5, kk = i & 31;
            sB[kk][nl] = wc_W[(bn + nl) * 2 * F_ + k0 + kk];
        }
        __syncthreads();
        #pragma unroll
        for (int kk = 0; kk < PBK; kk++) {
            float a[4], bb[4];
            #pragma unroll
            for (int i = 0; i < 4; i++) a[i] = sA[tr * 4 + i][kk];
            #pragma unroll
            for (int j = 0; j < 4; j++) bb[j] = sB[kk][tc * 4 + j];
            #pragma unroll
            for (int i = 0; i < 4; i++)
                #pragma unroll
                for (int j = 0; j < 4; j++) acc[i][j] += a[i] * bb[j];
        }
        __syncthreads();
    }
    #pragma unroll
    for (int i = 0; i < 4; i++) {
        int rr = rr0 + tr * 4 + i;
        #pragma unroll
        for (int j = 0; j < 4; j++) {
            int n = bn + tc * 4 + j;
            float s = acc[i][j] + wc_b[n];
            g_alpha[rr * F_ + n] = 1.f / (1.f + expf(-s));
        }
    }
}

// smem byte offsets
#define SM_RED 0                     // 128 B
#define SM_XS  128                   // 2*128 floats = 1024 B
#define SM_A   2048                  // 4 x 8KB A slots (S0..S3)
#define SM_W   (SM_A + 32768)        // weights: WHI 96KB (12 chunks x 8KB) + WLO 96KB
#define SMEM_BYTES (SM_W + 196608)   // 231424

// 64x64x64 bf16 split-MMA chunk: A hi at abase, A lo at abase+8192; B resident
__device__ __forceinline__ void mma_chunk(unsigned abase, unsigned whi, unsigned wlo,
                                          bool has_alo, float acc[4][4],
                                          int lane, int wr, int wcl) {
    const unsigned ahi = abase, alo = abase + 8192u;
    const int arow = wr * 16 + (lane & 15);
    const int aswz = arow & 7;
    #pragma unroll
    for (int ks = 0; ks < 4; ks++) {
        const int achk = ks * 2 + (lane >> 4);
        const unsigned aoff = (unsigned)(arow * 128 + ((achk ^ aswz) << 4));
        uint32_t Ahi[4], Alo[4];
        ldsm_x4(Ahi, ahi + aoff);
        if (has_alo) ldsm_x4(Alo, alo + aoff);
        uint32_t Bhi[8], Blo[8];
        #pragma unroll
        for (int pair = 0; pair < 2; pair++) {
            const int brow = wcl * 32 + pair * 16 + ((lane >> 4) << 3) + (lane & 7);
            const int bchk = ks * 2 + ((lane >> 3) & 1);
            const unsigned boff = (unsigned)(brow * 128 + ((bchk ^ (brow & 7)) << 4));
            ldsm_x4(Bhi + pair * 4, whi + boff);
            ldsm_x4(Blo + pair * 4, wlo + boff);
        }
        #pragma unroll
        for (int nb = 0; nb < 4; nb++) {
            mma16816(acc[nb], Ahi, Bhi + nb * 2);
            if (has_alo) mma16816(acc[nb], Alo, Bhi + nb * 2);
            mma16816(acc[nb], Ahi, Blo + nb * 2);
        }
    }
}

// ---------------- the persistent main kernel ----------------
__global__ __launch_bounds__(THREADS_MAIN, 1) void k_main(
    const float* __restrict__ x_all, const float* __restrict__ m_all,
    const float* __restrict__ tx_all, const float* __restrict__ ev_all,
    const float* __restrict__ hist_b, const float* __restrict__ feat_b,
    float* __restrict__ out) {
    extern __shared__ char smem[];
    const unsigned sm = (unsigned)__cvta_generic_to_shared(smem);
    float* red = (float*)(smem + SM_RED);
    float* xs  = (float*)(smem + SM_XS);
    float* Gs  = (float*)(smem + SM_A + 16384);  // aliases S2,S3 after all P2 mma

    const int tid = threadIdx.x;
    const int lane = tid & 31;
    const int wid = tid >> 5;
    const int wr = wid & 3, wcl = wid >> 2;      // warp 16x32 tile in 64x64
    const int bi = blockIdx.x;
    const int rg = bi / 34, ct = bi % 34;        // row-group, col-tile
    const int row0 = rg * 64;
    const bool is_hist = (ct >= 32);
    const int nb0 = is_hist ? (2048 + (ct - 32) * 64) : (ct * 64);
    const unsigned S0 = sm + SM_A, S1 = S0 + 8192u, S2 = S0 + 16384u, S3 = S0 + 24576u;
    const unsigned WHI = sm + SM_W, WLO = sm + SM_W + 98304u;
    unsigned* myG = g_flagG + (rg * 32 + (is_hist ? 0 : ct)) * 8;
    unsigned* myH = g_flagH + (rg * 2 + (ct - 32)) * 8;
    unsigned* myC = g_flagC + (rg * 32 + ct) * 8;

    // ---- one-time: resident weight load (12 chunks hi + lo) ----
    for (int i = tid; i < 12288; i += THREADS_MAIN) {
        int mat = i / 6144, rem = i - mat * 6144;
        int c = rem >> 9, g = rem & 511, r = g >> 3, p = g & 7;
        unsigned dst = (mat ? WLO : WHI) + (unsigned)(c * 8192 + r * 128 + ((p ^ (r & 7)) << 4));
        const __nv_bfloat16* src = (mat ? g_Blo : g_Bhi) + (size_t)(nb0 + r) * 768 + c * 64 + p * 8;
        cpa16(dst, src);
    }
    cp_commit();
    cp_wait0();
    __syncthreads();

    float cstate[4] = {0.f, 0.f, 0.f, 0.f};

    for (int t = 0; t < T_; t++) {
        if (t > 0) waitflags(g_flagG + rg * 32 * 8, 32, (unsigned)t);

        float acc[4][4] = {};

        // ============ P1: K 256..768, A = hdec (hi/lo), weight chunks 4..11 ============
        {
            for (int i = tid; i < 1024; i += THREADS_MAIN) {
                int mat = i >> 9, g = i & 511, r = g >> 3, p = g & 7;
                unsigned dst = (mat ? S1 : S0) + (unsigned)(r * 128 + ((p ^ (r & 7)) << 4));
                const __nv_bfloat16* src = (mat ? g_hd16lo : g_hd16hi) + (row0 + r) * H_ + p * 8;
                cpa16(dst, src);
            }
            cp_commit();
            for (int c = 0; c < 8; c++) {
                cp_wait0();
                __syncthreads();
                if (c < 7) {
                    int k0 = (c + 1) * 64;
                    unsigned bb = ((c + 1) & 1) ? S2 : S0;
                    for (int i = tid; i < 1024; i += THREADS_MAIN) {
                        int mat = i >> 9, g = i & 511, r = g >> 3, p = g & 7;
                        unsigned dst = bb + (unsigned)(mat * 8192 + r * 128 + ((p ^ (r & 7)) << 4));
                        const __nv_bfloat16* src = (mat ? g_hd16lo : g_hd16hi) + (row0 + r) * H_ + k0 + p * 8;
                        cpa16(dst, src);
                    }
                    cp_commit();
                }
                mma_chunk((c & 1) ? S2 : S0, WHI + (4 + c) * 8192u, WLO + (4 + c) * 8192u,
                          true, acc, lane, wr, wcl);
            }
        }

        if (is_hist) {
            // write x_hist (+hist_b) from register acc, signal H
            const int r0 = wr * 16 + (lane >> 2);
            const int c0g = wcl * 32 + (lane & 3) * 2;
            #pragma unroll
            for (int nb = 0; nb < 4; nb++) {
                #pragma unroll
                for (int q = 0; q < 4; q++) {
                    int r = r0 + ((q >> 1) << 3);
                    int fc = (ct - 32) * 64 + c0g + nb * 8 + (q & 1);
                    __stcg(&g_xhist[(row0 + r) * F_ + fc], acc[nb][q] + hist_b[fc]);
                }
            }
            signalflag(myH, (unsigned)(t + 1));
            continue;   // hist CTA: no chain / P2; next step waits G
        }

        // ---- gate CTA: prestage P2 m-chunks (independent of chain) into S0,S1 ----
        if (t < T_ - 1) {
            for (int i = tid; i < 1024; i += THREADS_MAIN) {
                int mat = i >> 9, g = i & 511, r = g >> 3, p = g & 7;
                unsigned dst = (mat ? S1 : S0) + (unsigned)(r * 128 + ((p ^ (r & 7)) << 4));
                const __nv_bfloat16* src = g_m16 + ((size_t)(row0 + r) * T_ + t) * F_ + mat * 64 + p * 8;
                cpa16(dst, src);
            }
            cp_commit();   // group G1 (m)
        }

        // ============ chain: own 2 rows (row0+2ct, +1) ============
        waitflags(g_flagH + rg * 2 * 8, 2, (unsigned)(t + 1));
        {
            const int rr = tid >> 7, f = tid & 127;
            const int prow = row0 + 2 * ct + rr;
            float xh = __ldcg(&g_xhist[prow * F_ + f]);
            int base = (prow * T_ + t) * F_ + f;
            float mv = m_all[base], xv = x_all[base];
            xs[rr * 128 + f] = mv * xv + (1.f - mv) * xh;
            __syncthreads();
            float z = feat_b[f];
            const float* xrow = xs + rr * 128;
            #pragma unroll 8
            for (int k = 0; k < 128; k++) z += xrow[k] * g_featT[k * F_ + f];
            float al = g_alpha[((size_t)t * B_ + prow) * F_ + f];
            float ch = al * z + (1.f - al) * xh;
            float cc = mv * xv + (1.f - mv) * ch;
            out[base] = cc;
            __nv_bfloat16 hi = __float2bfloat16(cc);
            __stcg(&g_cc16hi[prow * F_ + f], hi);
            __stcg(&g_cc16lo[prow * F_ + f], __float2bfloat16(cc - __bfloat162float(hi)));
            float tg = tx_all[base], evv = ev_all[base];
            float e1 = xh - tg, e2 = z - tg, e3 = ch - tg;
            float l = evv * (e1 * e1 + e2 * e2 + e3 * e3);
            #pragma unroll
            for (int off = 16; off > 0; off >>= 1) l += __shfl_down_sync(0xffffffffu, l, off);
            int ln = tid & 31, w = tid >> 5;
            if (ln == 0) red[w] = l;
            __syncthreads();
            if (tid == 0) {
                float tot = 0.f;
                #pragma unroll
                for (int i = 0; i < 8; i++) tot += red[i];
                atomicAdd(&g_loss, (double)tot / ((double)g_denom[t] * (double)T_));
            }
        }
        if (t == T_ - 1) break;
        signalflag(myC, (unsigned)(t + 1));

        // ============ P2: chunks m2,m3 (prestaged), cc0, cc1; then LSTM ============
        waitflags(g_flagC + rg * 32 * 8, 32, (unsigned)(t + 1));
        {
            // stage cc0 (K 0..63) hi->S2, lo->S3
            for (int i = tid; i < 1024; i += THREADS_MAIN) {
                int mat = i >> 9, g = i & 511, r = g >> 3, p = g & 7;
                unsigned dst = (mat ? S3 : S2) + (unsigned)(r * 128 + ((p ^ (r & 7)) << 4));
                const __nv_bfloat16* src = (mat ? g_cc16lo : g_cc16hi) + (row0 + r) * F_ + p * 8;
                cpa16(dst, src);
            }
            cp_commit();   // group G2 (cc0)
            cp_wait1();    // m (G1) arrived
            __syncthreads();
            mma_chunk(S0, WHI + 2 * 8192u, WLO + 2 * 8192u, false, acc, lane, wr, wcl);  // m2
            mma_chunk(S1, WHI + 3 * 8192u, WLO + 3 * 8192u, false, acc, lane, wr, wcl);  // m3
            __syncthreads();   // m slots free
            // stage cc1 (K 64..127) hi->S0, lo->S1
            for (int i = tid; i < 1024; i += THREADS_MAIN) {
                int mat = i >> 9, g = i & 511, r = g >> 3, p = g & 7;
                unsigned dst = (mat ? S1 : S0) + (unsigned)(r * 128 + ((p ^ (r & 7)) << 4));
                const __nv_bfloat16* src = (mat ? g_cc16lo : g_cc16hi) + (row0 + r) * F_ + 64 + p * 8;
                cpa16(dst, src);
            }
            cp_commit();   // group G3 (cc1)
            cp_wait1();    // cc0 arrived
            __syncthreads();
            mma_chunk(S2, WHI + 0 * 8192u, WLO + 0 * 8192u, true, acc, lane, wr, wcl);   // cc0
            cp_wait0();    // cc1 arrived
            __syncthreads();
            mma_chunk(S0, WHI + 1 * 8192u, WLO + 1 * 8192u, true, acc, lane, wr, wcl);   // cc1
            __syncthreads();
            // epilogue: Gs (at S2,S3) = acc + bias
            {
                const int r0 = wr * 16 + (lane >> 2);
                const int c0g = wcl * 32 + (lane & 3) * 2;
                #pragma unroll
                for (int nb = 0; nb < 4; nb++) {
                    #pragma unroll
                    for (int q = 0; q < 4; q++) {
                        int r = r0 + ((q >> 1) << 3);
                        int c = c0g + nb * 8 + (q & 1);
                        Gs[r * 64 + c] = acc[nb][q] + g_biasp[ct * 64 + c];
                    }
                }
            }
            __syncthreads();
            // LSTM on block-exclusive cells (64 rows x 16 j's), c-state in regs
            #pragma unroll
            for (int u = 0; u < 4; u++) {
                int cell = u * 256 + tid;
                int r = cell >> 4, jj = cell & 15;
                float ig = Gs[r * 64 + jj];
                float fg = Gs[r * 64 + 16 + jj];
                float gg = Gs[r * 64 + 32 + jj];
                float og = Gs[r * 64 + 48 + jj];
                float cn = sigf(fg) * cstate[u] + sigf(ig) * tanhf(gg);
                cstate[u] = cn;
                float h = sigf(og) * tanhf(cn);
                int gidx = (row0 + r) * H_ + ct * 16 + jj;
                float hd = h * g_gammah[(size_t)(t + 1) * B_ * H_ + gidx];
                __nv_bfloat16 hi = __float2bfloat16(hd);
                __stcg(&g_hd16hi[gidx], hi);
                __stcg(&g_hd16lo[gidx], __float2bfloat16(hd - __bfloat162float(hi)));
            }
        }
        signalflag(myG, (unsigned)(t + 1));
    }
}

// ---------------- finalize ----------------
__global__ void k_finish(float* __restrict__ out, int out_size) {
    out[out_size - 1] = (float)g_loss;
}

// ---------------- launch ----------------
extern "C" void kernel_launch(void* const* d_in, const int* in_sizes, int n_in,
                              void* d_out, int out_size) {
    const float* x      = (const float*)d_in[0];
    const float* m      = (const float*)d_in[1];
    const float* d      = (const float*)d_in[2];
    const float* tx     = (const float*)d_in[3];
    const float* ev     = (const float*)d_in[4];
    const float* td_h_W = (const float*)d_in[5];
    const float* td_h_b = (const float*)d_in[6];
    const float* td_x_W = (const float*)d_in[7];
    const float* td_x_b = (const float*)d_in[8];
    const float* hist_W = (const float*)d_in[9];
    const float* hist_b = (const float*)d_in[10];
    const float* feat_W = (const float*)d_in[11];
    const float* feat_b = (const float*)d_in[12];
    const float* wc_W   = (const float*)d_in[13];
    const float* wc_b   = (const float*)d_in[14];
    const float* W_ih   = (const float*)d_in[15];
    const float* W_hh   = (const float*)d_in[16];
    const float* b_ih   = (const float*)d_in[17];
    const float* b_hh   = (const float*)d_in[18];
    float* out = (float*)d_out;

    static int smem_set = 0;
    if (!smem_set) {
        cudaFuncSetAttribute(k_main, cudaFuncAttributeMaxDynamicSharedMemorySize, SMEM_BYTES);
        smem_set = 1;
    }

    k_init<<<512, 256>>>(feat_W);
    k_prep<<<1024, 256>>>(W_ih, W_hh, hist_W, b_ih, b_hh, m);
    k_denom<<<T_, 256>>>(ev);
    k_gammah<<<dim3(H_ / PBN, (T_ * B_) / PBM), 256>>>(d, td_h_W, td_h_b);
    k_alpha<<<dim3(F_ / PBN, (T_ * B_) / PBM), 256>>>(d, m, td_x_W, td_x_b, wc_W, wc_b);
    k_main<<<GRID_MAIN, THREADS_MAIN, SMEM_BYTES>>>(x, m, tx, ev, hist_b, feat_b, out);
    k_finish<<<1, 1>>>(out, out_size);
}